// round 12
// baseline (speedup 1.0000x reference)
#include <cuda_runtime.h>
#include <cuda_bf16.h>
#include <cuda_fp16.h>
#include <stdint.h>
#include <math.h>

#define B_   8
#define T_   2048
#define DIM_ 512
#define NH_  8
#define NKV_ 4
#define HD_  64
#define KVD_ (NKV_*HD_)
#define BT_  (B_*T_)

// fp32 scratch
__device__ float g_q[(size_t)BT_*DIM_];
__device__ float g_k[(size_t)BT_*KVD_];
__device__ float g_y[(size_t)BT_*DIM_];
// fp16 scratch
__device__ uint16_t g_qf[(size_t)BT_*DIM_];
__device__ uint16_t g_kf[(size_t)BT_*KVD_];
__device__ uint16_t g_vf[(size_t)BT_*KVD_];
// rope tables
__device__ float g_cos[T_*32], g_sin[T_*32];

#define MMA_BF16(d, a, b) asm volatile( \
  "mma.sync.aligned.m16n8k16.row.col.f32.bf16.bf16.f32 " \
  "{%0,%1,%2,%3}, {%4,%5,%6,%7}, {%8,%9}, {%0,%1,%2,%3};\n" \
  : "+f"(d[0]), "+f"(d[1]), "+f"(d[2]), "+f"(d[3]) \
  : "r"(a[0]), "r"(a[1]), "r"(a[2]), "r"(a[3]), "r"(b[0]), "r"(b[1]))

#define MMA_F16(d, a, b) asm volatile( \
  "mma.sync.aligned.m16n8k16.row.col.f32.f16.f16.f32 " \
  "{%0,%1,%2,%3}, {%4,%5,%6,%7}, {%8,%9}, {%0,%1,%2,%3};\n" \
  : "+f"(d[0]), "+f"(d[1]), "+f"(d[2]), "+f"(d[3]) \
  : "r"(a[0]), "r"(a[1]), "r"(a[2]), "r"(a[3]), "r"(b[0]), "r"(b[1]))

#define LDMX2T(r0, r1, a) asm volatile( \
  "ldmatrix.sync.aligned.m8n8.x2.trans.shared.b16 {%0,%1}, [%2];" \
  : "=r"(r0), "=r"(r1) : "r"(a))

__device__ __forceinline__ uint32_t f2h2(float a, float b)
{
    __half2 h = __floats2half2_rn(a, b);
    return *(uint32_t*)&h;
}

// cheap truncation split: hi = top16(f) (bf16 trunc), lo = trunc_bf16(f - hi)
__device__ __forceinline__ void pack4c(float4 f, uint32_t* hi, uint32_t* lo)
{
    uint32_t x0 = __float_as_uint(f.x), x1 = __float_as_uint(f.y);
    uint32_t x2 = __float_as_uint(f.z), x3 = __float_as_uint(f.w);
    hi[0] = __byte_perm(x0, x1, 0x7632);
    hi[1] = __byte_perm(x2, x3, 0x7632);
    float l0 = f.x - __uint_as_float(x0 & 0xffff0000u);
    float l1 = f.y - __uint_as_float(x1 & 0xffff0000u);
    float l2 = f.z - __uint_as_float(x2 & 0xffff0000u);
    float l3 = f.w - __uint_as_float(x3 & 0xffff0000u);
    lo[0] = __byte_perm(__float_as_uint(l0), __float_as_uint(l1), 0x7632);
    lo[1] = __byte_perm(__float_as_uint(l2), __float_as_uint(l3), 0x7632);
}

// rope cos/sin tables (double-precision freq)
__global__ void rope_tables(float* __restrict__ ctab, float* __restrict__ stab)
{
    int i = blockIdx.x * blockDim.x + threadIdx.x;
    if (i >= T_*32) return;
    int t = i >> 5, j = i & 31;
    double invf = pow(10000.0, -(double)(2*j) / (double)HD_);
    float ang = (float)((double)t * invf);
    float s, c;
    sincosf(ang, &s, &c);
    ctab[i] = c; stab[i] = s;
}

// ---------------------------------------------------------------------------
// bf16 3-split tensor-core GEMM:  C[M,N] = A[M,K] @ W[N,K]^T
// Block 128x128, BK=16, 16 warps (4x4), warp tile 32x32.
// Column blocks are 128-wide -> A gmem traffic halves vs GBN=64.
// Cf16 != null -> fp16 epilogue.
// ---------------------------------------------------------------------------
#define GBM 128
#define GBN 128
#define AST 12

__global__ __launch_bounds__(512) void gemm_bf16x2(const float* __restrict__ A,
                                                   const float* __restrict__ W,
                                                   float* __restrict__ C,
                                                   uint16_t* __restrict__ Cf16,
                                                   int M, int N, int K)
{
    __shared__ uint32_t As[2][GBM * AST];
    __shared__ uint32_t Bs[2][GBN * AST];

    const int tid  = threadIdx.x;
    const int wid  = tid >> 5, lane = tid & 31;
    const int g    = lane >> 2, tig = lane & 3;
    const int wm   = wid & 3, wn = wid >> 2;
    const int row0 = blockIdx.y * GBM, col0 = blockIdx.x * GBN;

    const int ar = tid >> 2, ak = tid & 3;   // one float4 per thread, A and B

    float acc[2][4][4];
    #pragma unroll
    for (int i = 0; i < 2; i++)
        #pragma unroll
        for (int j = 0; j < 4; j++)
            #pragma unroll
            for (int c = 0; c < 4; c++) acc[i][j][c] = 0.f;

    float4 pa = *(const float4*)(A + (size_t)(row0 + ar) * K + ak * 4);
    float4 pb = *(const float4*)(W + (size_t)(col0 + ar) * K + ak * 4);

    for (int k0 = 0; k0 < K; k0 += 16) {
        uint32_t h[2], l[2];
        pack4c(pa, h, l);
        As[0][ar * AST + ak * 2] = h[0]; As[0][ar * AST + ak * 2 + 1] = h[1];
        As[1][ar * AST + ak * 2] = l[0]; As[1][ar * AST + ak * 2 + 1] = l[1];
        pack4c(pb, h, l);
        Bs[0][ar * AST + ak * 2] = h[0]; Bs[0][ar * AST + ak * 2 + 1] = h[1];
        Bs[1][ar * AST + ak * 2] = l[0]; Bs[1][ar * AST + ak * 2 + 1] = l[1];
        __syncthreads();

        if (k0 + 16 < K) {
            pa = *(const float4*)(A + (size_t)(row0 + ar) * K + k0 + 16 + ak * 4);
            pb = *(const float4*)(W + (size_t)(col0 + ar) * K + k0 + 16 + ak * 4);
        }

        uint32_t afh[2][4], afl[2][4], bfh[4][2], bfl[4][2];
        #pragma unroll
        for (int mt = 0; mt < 2; mt++) {
            int rb = (wm * 32 + mt * 16) * AST;
            afh[mt][0] = As[0][rb + g * AST + tig];
            afh[mt][1] = As[0][rb + (g + 8) * AST + tig];
            afh[mt][2] = As[0][rb + g * AST + tig + 4];
            afh[mt][3] = As[0][rb + (g + 8) * AST + tig + 4];
            afl[mt][0] = As[1][rb + g * AST + tig];
            afl[mt][1] = As[1][rb + (g + 8) * AST + tig];
            afl[mt][2] = As[1][rb + g * AST + tig + 4];
            afl[mt][3] = As[1][rb + (g + 8) * AST + tig + 4];
        }
        #pragma unroll
        for (int nt = 0; nt < 4; nt++) {
            int cb = (wn * 32 + nt * 8 + g) * AST;
            bfh[nt][0] = Bs[0][cb + tig];
            bfh[nt][1] = Bs[0][cb + tig + 4];
            bfl[nt][0] = Bs[1][cb + tig];
            bfl[nt][1] = Bs[1][cb + tig + 4];
        }

        #pragma unroll
        for (int mt = 0; mt < 2; mt++)
            #pragma unroll
            for (int nt = 0; nt < 4; nt++) {
                MMA_BF16(acc[mt][nt], afh[mt], bfh[nt]);
                MMA_BF16(acc[mt][nt], afh[mt], bfl[nt]);
                MMA_BF16(acc[mt][nt], afl[mt], bfh[nt]);
            }
        __syncthreads();
    }

    if (Cf16) {
        #pragma unroll
        for (int mt = 0; mt < 2; mt++)
            #pragma unroll
            for (int nt = 0; nt < 4; nt++) {
                int row = row0 + wm * 32 + mt * 16 + g;
                int col = col0 + wn * 32 + nt * 8 + 2 * tig;
                ((uint32_t*)Cf16)[((size_t)row * N + col) >> 1] =
                    f2h2(acc[mt][nt][0], acc[mt][nt][1]);
                ((uint32_t*)Cf16)[((size_t)(row + 8) * N + col) >> 1] =
                    f2h2(acc[mt][nt][2], acc[mt][nt][3]);
            }
    } else {
        #pragma unroll
        for (int mt = 0; mt < 2; mt++)
            #pragma unroll
            for (int nt = 0; nt < 4; nt++) {
                int row = row0 + wm * 32 + mt * 16 + g;
                int col = col0 + wn * 32 + nt * 8 + 2 * tig;
                *(float2*)(C + (size_t)row * N + col) =
                    make_float2(acc[mt][nt][0], acc[mt][nt][1]);
                *(float2*)(C + (size_t)(row + 8) * N + col) =
                    make_float2(acc[mt][nt][2], acc[mt][nt][3]);
            }
    }
}

// ---------------------------------------------------------------------------
// Fused RMSNorm + RoPE (table) + scale -> fp16. One launch covers q and k.
// ---------------------------------------------------------------------------
__global__ void rms_rope_f16(const float* __restrict__ qsrc,
                             const float* __restrict__ ksrc,
                             uint16_t* __restrict__ qdst,
                             uint16_t* __restrict__ kdst,
                             const float* __restrict__ ctab,
                             const float* __restrict__ stab)
{
    int w    = (blockIdx.x * blockDim.x + threadIdx.x) >> 5;
    int lane = threadIdx.x & 31;
    const int QROWS = BT_ * NH_;
    if (w >= QROWS + BT_ * NKV_) return;

    const float* src;
    uint16_t* dst;
    int t;
    float scale;
    if (w < QROWS) {
        src = qsrc + (size_t)w * HD_;
        dst = qdst + (size_t)w * HD_;
        t = (w / NH_) % T_;
        scale = 0.125f;
    } else {
        int wk = w - QROWS;
        src = ksrc + (size_t)wk * HD_;
        dst = kdst + (size_t)wk * HD_;
        t = (wk / NKV_) % T_;
        scale = 1.0f;
    }

    float x1 = src[lane], x2 = src[lane + 32];
    float ss = x1 * x1 + x2 * x2;
    #pragma unroll
    for (int o = 16; o; o >>= 1) ss += __shfl_xor_sync(0xffffffffu, ss, o);
    float sc = rsqrtf(ss * (1.0f / HD_) + 1.1920928955078125e-07f);
    x1 *= sc; x2 *= sc;

    float c = ctab[t * 32 + lane], s = stab[t * 32 + lane];
    float o1 = ( x1 * c + x2 * s) * scale;
    float o2 = (-x1 * s + x2 * c) * scale;

    __half h1 = __float2half_rn(o1), h2 = __float2half_rn(o2);
    dst[lane]      = *(uint16_t*)&h1;
    dst[lane + 32] = *(uint16_t*)&h2;
}

// ---------------------------------------------------------------------------
// Tensor-core causal GQA flash attention, single-product fp16.
// |s| <= 8 -> p in [e^-8, e^8]: inside fp16 normal range, no max needed.
// ---------------------------------------------------------------------------
__global__ __launch_bounds__(128) void flash_tc(
    const uint16_t* __restrict__ qf, const uint16_t* __restrict__ kf,
    const uint16_t* __restrict__ vf, float* __restrict__ y)
{
    __shared__ uint32_t K_s[64*36], V_s[64*36];

    const int b = blockIdx.z, h = blockIdx.y;
    const int m0 = blockIdx.x * 64;
    const int kvh = h >> 1;
    const int tid = threadIdx.x, wid = tid >> 5, lane = tid & 31;
    const int g = lane >> 2, tig = lane & 3;
    const int row0 = m0 + wid * 16;

    const uint32_t* q32 = (const uint32_t*)qf;
    const uint32_t* k32 = (const uint32_t*)kf;
    const uint32_t* v32 = (const uint32_t*)vf;

    uint32_t qfr[4][4];
    {
        size_t q0 = ((size_t)(b * T_ + row0 + g) * NH_ + h) * 32;
        size_t q1 = ((size_t)(b * T_ + row0 + g + 8) * NH_ + h) * 32;
        #pragma unroll
        for (int kk = 0; kk < 4; kk++) {
            qfr[kk][0] = q32[q0 + kk*8 + tig];
            qfr[kk][1] = q32[q1 + kk*8 + tig];
            qfr[kk][2] = q32[q0 + kk*8 + 4 + tig];
            qfr[kk][3] = q32[q1 + kk*8 + 4 + tig];
        }
    }

    float o[8][4];
    #pragma unroll
    for (int nt = 0; nt < 8; nt++)
        #pragma unroll
        for (int c = 0; c < 4; c++) o[nt][c] = 0.f;
    float lsum0 = 0.f, lsum1 = 0.f;

    uint32_t v_base = (uint32_t)__cvta_generic_to_shared(V_s);

    for (int n0 = 0; n0 <= m0; n0 += 64) {
        #pragma unroll
        for (int it = 0; it < 4; it++) {
            int e = it * 128 + tid;
            int j = e >> 3, dq = (e & 7) * 4;
            size_t src = ((size_t)(b * T_ + n0 + j) * NKV_ + kvh) * 32 + dq;
            int dst = j * 36 + dq;
            *(uint4*)&K_s[dst] = *(const uint4*)&k32[src];
            *(uint4*)&V_s[dst] = *(const uint4*)&v32[src];
        }
        __syncthreads();

        float sfr[8][4];
        #pragma unroll
        for (int nt = 0; nt < 8; nt++) {
            #pragma unroll
            for (int c = 0; c < 4; c++) sfr[nt][c] = 0.f;
            #pragma unroll
            for (int kk = 0; kk < 4; kk++) {
                uint32_t bb[2];
                int bw = (nt*8 + g)*36 + kk*8 + tig;
                bb[0] = K_s[bw]; bb[1] = K_s[bw + 4];
                MMA_F16(sfr[nt], qfr[kk], bb);
            }
        }

        uint32_t pfr[4][4];
        const bool diag = (n0 == m0);
        #pragma unroll
        for (int nt = 0; nt < 8; nt++) {
            float p0 = __expf(sfr[nt][0]);
            float p1 = __expf(sfr[nt][1]);
            float p2 = __expf(sfr[nt][2]);
            float p3 = __expf(sfr[nt][3]);
            if (diag) {
                int col = n0 + nt*8 + 2*tig;
                int r0 = row0 + g, r1 = row0 + g + 8;
                if (col     > r0) p0 = 0.f;
                if (col + 1 > r0) p1 = 0.f;
                if (col     > r1) p2 = 0.f;
                if (col + 1 > r1) p3 = 0.f;
            }
            lsum0 += p0 + p1;
            lsum1 += p2 + p3;
            int kk = nt >> 1, s = (nt & 1) * 2;
            pfr[kk][s]   = f2h2(p0, p1);
            pfr[kk][s+1] = f2h2(p2, p3);
        }

        #pragma unroll
        for (int nt = 0; nt < 8; nt++) {
            #pragma unroll
            for (int kk = 0; kk < 4; kk++) {
                uint32_t off = ((16*kk + (lane & 15)) * 36 + nt*4) * 4;
                uint32_t bb[2];
                LDMX2T(bb[0], bb[1], v_base + off);
                MMA_F16(o[nt], pfr[kk], bb);
            }
        }
        __syncthreads();
    }

    lsum0 += __shfl_xor_sync(0xffffffffu, lsum0, 1);
    lsum0 += __shfl_xor_sync(0xffffffffu, lsum0, 2);
    lsum1 += __shfl_xor_sync(0xffffffffu, lsum1, 1);
    lsum1 += __shfl_xor_sync(0xffffffffu, lsum1, 2);
    float i0 = 1.f / lsum0, i1 = 1.f / lsum1;

    float* y0 = y + ((size_t)(b * T_ + row0 + g) * NH_ + h) * HD_;
    float* y1 = y + ((size_t)(b * T_ + row0 + g + 8) * NH_ + h) * HD_;
    #pragma unroll
    for (int nt = 0; nt < 8; nt++) {
        int col = nt*8 + 2*tig;
        *(float2*)(y0 + col) = make_float2(o[nt][0] * i0, o[nt][1] * i0);
        *(float2*)(y1 + col) = make_float2(o[nt][2] * i1, o[nt][3] * i1);
    }
}

// ---------------------------------------------------------------------------
extern "C" void kernel_launch(void* const* d_in, const int* in_sizes, int n_in,
                              void* d_out, int out_size)
{
    const float* x  = (const float*)d_in[0];
    const float* Wq = (const float*)d_in[1];
    const float* Wk = (const float*)d_in[2];
    const float* Wv = (const float*)d_in[3];
    const float* Wp = (const float*)d_in[4];
    float* out = (float*)d_out;

    float *q, *k, *y, *ctab, *stab;
    cudaGetSymbolAddress((void**)&q, g_q);
    cudaGetSymbolAddress((void**)&k, g_k);
    cudaGetSymbolAddress((void**)&y, g_y);
    cudaGetSymbolAddress((void**)&ctab, g_cos);
    cudaGetSymbolAddress((void**)&stab, g_sin);
    uint16_t *qf, *kf, *vf;
    cudaGetSymbolAddress((void**)&qf, g_qf);
    cudaGetSymbolAddress((void**)&kf, g_kf);
    cudaGetSymbolAddress((void**)&vf, g_vf);

    // QKV projections (bf16 3-split, 128-wide col tiles; V writes fp16 directly)
    gemm_bf16x2<<<dim3(DIM_/GBN, BT_/GBM), 512>>>(x, Wq, q, nullptr, BT_, DIM_, DIM_);
    gemm_bf16x2<<<dim3(KVD_/GBN, BT_/GBM), 512>>>(x, Wk, k, nullptr, BT_, KVD_, DIM_);
    gemm_bf16x2<<<dim3(KVD_/GBN, BT_/GBM), 512>>>(x, Wv, nullptr, vf, BT_, KVD_, DIM_);

    // rope tables, then fused rmsnorm+rope -> fp16 q,k
    rope_tables<<<(T_*32 + 255)/256, 256>>>(ctab, stab);
    rms_rope_f16<<<((BT_*NH_ + BT_*NKV_)*32 + 255)/256, 256>>>(q, k, qf, kf, ctab, stab);

    // fp16 tensor-core causal flash attention
    flash_tc<<<dim3(T_/64, NH_, B_), 128>>>(qf, kf, vf, y);

    // Output projection
    gemm_bf16x2<<<dim3(DIM_/GBN, BT_/GBM), 512>>>(y, Wp, out, nullptr, BT_, DIM_, DIM_);
}

// round 13
// speedup vs baseline: 1.0387x; 1.0387x over previous
#include <cuda_runtime.h>
#include <cuda_bf16.h>
#include <cuda_fp16.h>
#include <stdint.h>
#include <math.h>

#define B_   8
#define T_   2048
#define DIM_ 512
#define NH_  8
#define NKV_ 4
#define HD_  64
#define KVD_ (NKV_*HD_)
#define BT_  (B_*T_)

// fp32 scratch
__device__ float g_q[(size_t)BT_*DIM_];
__device__ float g_k[(size_t)BT_*KVD_];
__device__ float g_y[(size_t)BT_*DIM_];
// fp16 scratch
__device__ uint16_t g_qf[(size_t)BT_*DIM_];
__device__ uint16_t g_kf[(size_t)BT_*KVD_];
__device__ uint16_t g_vf[(size_t)BT_*KVD_];
// rope tables
__device__ float g_cos[T_*32], g_sin[T_*32];

#define MMA_BF16(d, a, b) asm volatile( \
  "mma.sync.aligned.m16n8k16.row.col.f32.bf16.bf16.f32 " \
  "{%0,%1,%2,%3}, {%4,%5,%6,%7}, {%8,%9}, {%0,%1,%2,%3};\n" \
  : "+f"(d[0]), "+f"(d[1]), "+f"(d[2]), "+f"(d[3]) \
  : "r"(a[0]), "r"(a[1]), "r"(a[2]), "r"(a[3]), "r"(b[0]), "r"(b[1]))

#define MMA_F16(d, a, b) asm volatile( \
  "mma.sync.aligned.m16n8k16.row.col.f32.f16.f16.f32 " \
  "{%0,%1,%2,%3}, {%4,%5,%6,%7}, {%8,%9}, {%0,%1,%2,%3};\n" \
  : "+f"(d[0]), "+f"(d[1]), "+f"(d[2]), "+f"(d[3]) \
  : "r"(a[0]), "r"(a[1]), "r"(a[2]), "r"(a[3]), "r"(b[0]), "r"(b[1]))

#define LDMX2T(r0, r1, a) asm volatile( \
  "ldmatrix.sync.aligned.m8n8.x2.trans.shared.b16 {%0,%1}, [%2];" \
  : "=r"(r0), "=r"(r1) : "r"(a))

__device__ __forceinline__ uint32_t f2h2(float a, float b)
{
    __half2 h = __floats2half2_rn(a, b);
    return *(uint32_t*)&h;
}

// cheap truncation split: hi = top16(f) (bf16 trunc), lo = trunc_bf16(f - hi)
__device__ __forceinline__ void pack4c(float4 f, uint32_t* hi, uint32_t* lo)
{
    uint32_t x0 = __float_as_uint(f.x), x1 = __float_as_uint(f.y);
    uint32_t x2 = __float_as_uint(f.z), x3 = __float_as_uint(f.w);
    hi[0] = __byte_perm(x0, x1, 0x7632);
    hi[1] = __byte_perm(x2, x3, 0x7632);
    float l0 = f.x - __uint_as_float(x0 & 0xffff0000u);
    float l1 = f.y - __uint_as_float(x1 & 0xffff0000u);
    float l2 = f.z - __uint_as_float(x2 & 0xffff0000u);
    float l3 = f.w - __uint_as_float(x3 & 0xffff0000u);
    lo[0] = __byte_perm(__float_as_uint(l0), __float_as_uint(l1), 0x7632);
    lo[1] = __byte_perm(__float_as_uint(l2), __float_as_uint(l3), 0x7632);
}

// rope cos/sin tables (double-precision freq)
__global__ void rope_tables(float* __restrict__ ctab, float* __restrict__ stab)
{
    int i = blockIdx.x * blockDim.x + threadIdx.x;
    if (i >= T_*32) return;
    int t = i >> 5, j = i & 31;
    double invf = pow(10000.0, -(double)(2*j) / (double)HD_);
    float ang = (float)((double)t * invf);
    float s, c;
    sincosf(ang, &s, &c);
    ctab[i] = c; stab[i] = s;
}

// ---------------------------------------------------------------------------
// bf16 3-split tensor-core GEMM (round-7 proven config):
// C[M,N] = A[M,K] @ W[N,K]^T. Block 128x64, BK=16, 8 warps, single-stage.
// Cf16 != null -> fp16 epilogue.
// ---------------------------------------------------------------------------
#define GBM 128
#define GBN 64
#define AST 12

__global__ __launch_bounds__(256) void gemm_bf16x2(const float* __restrict__ A,
                                                   const float* __restrict__ W,
                                                   float* __restrict__ C,
                                                   uint16_t* __restrict__ Cf16,
                                                   int M, int N, int K)
{
    __shared__ uint32_t As[2][GBM * AST];
    __shared__ uint32_t Bs[2][GBN * AST];

    const int tid  = threadIdx.x;
    const int wid  = tid >> 5, lane = tid & 31;
    const int g    = lane >> 2, tig = lane & 3;
    const int wm   = wid & 3, wn = wid >> 2;
    const int row0 = blockIdx.y * GBM, col0 = blockIdx.x * GBN;

    const int ar0 = (tid) >> 2,       ak0 = (tid & 3);
    const int ar1 = (256 + tid) >> 2, ak1 = (tid & 3);
    const int br  = tid >> 2,         bk  = tid & 3;

    float acc[2][4][4];
    #pragma unroll
    for (int i = 0; i < 2; i++)
        #pragma unroll
        for (int j = 0; j < 4; j++)
            #pragma unroll
            for (int c = 0; c < 4; c++) acc[i][j][c] = 0.f;

    float4 pa0 = *(const float4*)(A + (size_t)(row0 + ar0) * K + ak0 * 4);
    float4 pa1 = *(const float4*)(A + (size_t)(row0 + ar1) * K + ak1 * 4);
    float4 pb  = *(const float4*)(W + (size_t)(col0 + br ) * K + bk  * 4);

    for (int k0 = 0; k0 < K; k0 += 16) {
        uint32_t h[2], l[2];
        pack4c(pa0, h, l);
        As[0][ar0 * AST + ak0 * 2] = h[0]; As[0][ar0 * AST + ak0 * 2 + 1] = h[1];
        As[1][ar0 * AST + ak0 * 2] = l[0]; As[1][ar0 * AST + ak0 * 2 + 1] = l[1];
        pack4c(pa1, h, l);
        As[0][ar1 * AST + ak1 * 2] = h[0]; As[0][ar1 * AST + ak1 * 2 + 1] = h[1];
        As[1][ar1 * AST + ak1 * 2] = l[0]; As[1][ar1 * AST + ak1 * 2 + 1] = l[1];
        pack4c(pb, h, l);
        Bs[0][br * AST + bk * 2] = h[0]; Bs[0][br * AST + bk * 2 + 1] = h[1];
        Bs[1][br * AST + bk * 2] = l[0]; Bs[1][br * AST + bk * 2 + 1] = l[1];
        __syncthreads();

        if (k0 + 16 < K) {
            pa0 = *(const float4*)(A + (size_t)(row0 + ar0) * K + k0 + 16 + ak0 * 4);
            pa1 = *(const float4*)(A + (size_t)(row0 + ar1) * K + k0 + 16 + ak1 * 4);
            pb  = *(const float4*)(W + (size_t)(col0 + br ) * K + k0 + 16 + bk  * 4);
        }

        uint32_t afh[2][4], afl[2][4], bfh[4][2], bfl[4][2];
        #pragma unroll
        for (int mt = 0; mt < 2; mt++) {
            int rb = (wm * 32 + mt * 16) * AST;
            afh[mt][0] = As[0][rb + g * AST + tig];
            afh[mt][1] = As[0][rb + (g + 8) * AST + tig];
            afh[mt][2] = As[0][rb + g * AST + tig + 4];
            afh[mt][3] = As[0][rb + (g + 8) * AST + tig + 4];
            afl[mt][0] = As[1][rb + g * AST + tig];
            afl[mt][1] = As[1][rb + (g + 8) * AST + tig];
            afl[mt][2] = As[1][rb + g * AST + tig + 4];
            afl[mt][3] = As[1][rb + (g + 8) * AST + tig + 4];
        }
        #pragma unroll
        for (int nt = 0; nt < 4; nt++) {
            int cb = (wn * 32 + nt * 8 + g) * AST;
            bfh[nt][0] = Bs[0][cb + tig];
            bfh[nt][1] = Bs[0][cb + tig + 4];
            bfl[nt][0] = Bs[1][cb + tig];
            bfl[nt][1] = Bs[1][cb + tig + 4];
        }

        #pragma unroll
        for (int mt = 0; mt < 2; mt++)
            #pragma unroll
            for (int nt = 0; nt < 4; nt++) {
                MMA_BF16(acc[mt][nt], afh[mt], bfh[nt]);
                MMA_BF16(acc[mt][nt], afh[mt], bfl[nt]);
                MMA_BF16(acc[mt][nt], afl[mt], bfh[nt]);
            }
        __syncthreads();
    }

    if (Cf16) {
        #pragma unroll
        for (int mt = 0; mt < 2; mt++)
            #pragma unroll
            for (int nt = 0; nt < 4; nt++) {
                int row = row0 + wm * 32 + mt * 16 + g;
                int col = col0 + wn * 32 + nt * 8 + 2 * tig;
                ((uint32_t*)Cf16)[((size_t)row * N + col) >> 1] =
                    f2h2(acc[mt][nt][0], acc[mt][nt][1]);
                ((uint32_t*)Cf16)[((size_t)(row + 8) * N + col) >> 1] =
                    f2h2(acc[mt][nt][2], acc[mt][nt][3]);
            }
    } else {
        #pragma unroll
        for (int mt = 0; mt < 2; mt++)
            #pragma unroll
            for (int nt = 0; nt < 4; nt++) {
                int row = row0 + wm * 32 + mt * 16 + g;
                int col = col0 + wn * 32 + nt * 8 + 2 * tig;
                *(float2*)(C + (size_t)row * N + col) =
                    make_float2(acc[mt][nt][0], acc[mt][nt][1]);
                *(float2*)(C + (size_t)(row + 8) * N + col) =
                    make_float2(acc[mt][nt][2], acc[mt][nt][3]);
            }
    }
}

// ---------------------------------------------------------------------------
// Fused RMSNorm + RoPE (table) + scale -> fp16. One launch covers q and k.
// ---------------------------------------------------------------------------
__global__ void rms_rope_f16(const float* __restrict__ qsrc,
                             const float* __restrict__ ksrc,
                             uint16_t* __restrict__ qdst,
                             uint16_t* __restrict__ kdst,
                             const float* __restrict__ ctab,
                             const float* __restrict__ stab)
{
    int w    = (blockIdx.x * blockDim.x + threadIdx.x) >> 5;
    int lane = threadIdx.x & 31;
    const int QROWS = BT_ * NH_;
    if (w >= QROWS + BT_ * NKV_) return;

    const float* src;
    uint16_t* dst;
    int t;
    float scale;
    if (w < QROWS) {
        src = qsrc + (size_t)w * HD_;
        dst = qdst + (size_t)w * HD_;
        t = (w / NH_) % T_;
        scale = 0.125f;
    } else {
        int wk = w - QROWS;
        src = ksrc + (size_t)wk * HD_;
        dst = kdst + (size_t)wk * HD_;
        t = (wk / NKV_) % T_;
        scale = 1.0f;
    }

    float x1 = src[lane], x2 = src[lane + 32];
    float ss = x1 * x1 + x2 * x2;
    #pragma unroll
    for (int o = 16; o; o >>= 1) ss += __shfl_xor_sync(0xffffffffu, ss, o);
    float sc = rsqrtf(ss * (1.0f / HD_) + 1.1920928955078125e-07f);
    x1 *= sc; x2 *= sc;

    float c = ctab[t * 32 + lane], s = stab[t * 32 + lane];
    float o1 = ( x1 * c + x2 * s) * scale;
    float o2 = (-x1 * s + x2 * c) * scale;

    __half h1 = __float2half_rn(o1), h2 = __float2half_rn(o2);
    dst[lane]      = *(uint16_t*)&h1;
    dst[lane + 32] = *(uint16_t*)&h2;
}

// ---------------------------------------------------------------------------
// Tensor-core causal GQA flash attention, single-product fp16.
// BM=128 rows/block (8 warps x 16 rows), BN=64 KV tile -> KV tile visits
// drop ~2x vs BM=64 (Q reuse doubles). |s|<=8 -> no max-subtraction needed.
// ---------------------------------------------------------------------------
__global__ __launch_bounds__(256) void flash_tc(
    const uint16_t* __restrict__ qf, const uint16_t* __restrict__ kf,
    const uint16_t* __restrict__ vf, float* __restrict__ y)
{
    __shared__ uint32_t K_s[64*36], V_s[64*36];

    const int b = blockIdx.z, h = blockIdx.y;
    const int m0 = blockIdx.x * 128;
    const int kvh = h >> 1;
    const int tid = threadIdx.x, wid = tid >> 5, lane = tid & 31;
    const int g = lane >> 2, tig = lane & 3;
    const int row0 = m0 + wid * 16;

    const uint32_t* q32 = (const uint32_t*)qf;
    const uint32_t* k32 = (const uint32_t*)kf;
    const uint32_t* v32 = (const uint32_t*)vf;

    uint32_t qfr[4][4];
    {
        size_t q0 = ((size_t)(b * T_ + row0 + g) * NH_ + h) * 32;
        size_t q1 = ((size_t)(b * T_ + row0 + g + 8) * NH_ + h) * 32;
        #pragma unroll
        for (int kk = 0; kk < 4; kk++) {
            qfr[kk][0] = q32[q0 + kk*8 + tig];
            qfr[kk][1] = q32[q1 + kk*8 + tig];
            qfr[kk][2] = q32[q0 + kk*8 + 4 + tig];
            qfr[kk][3] = q32[q1 + kk*8 + 4 + tig];
        }
    }

    float o[8][4];
    #pragma unroll
    for (int nt = 0; nt < 8; nt++)
        #pragma unroll
        for (int c = 0; c < 4; c++) o[nt][c] = 0.f;
    float lsum0 = 0.f, lsum1 = 0.f;

    uint32_t v_base = (uint32_t)__cvta_generic_to_shared(V_s);

    for (int n0 = 0; n0 <= m0 + 64; n0 += 64) {
        // cooperative tile load: 512 uint4 over 256 threads (2 iters)
        #pragma unroll
        for (int it = 0; it < 2; it++) {
            int e = it * 256 + tid;
            int j = e >> 3, dq = (e & 7) * 4;
            size_t src = ((size_t)(b * T_ + n0 + j) * NKV_ + kvh) * 32 + dq;
            int dst = j * 36 + dq;
            *(uint4*)&K_s[dst] = *(const uint4*)&k32[src];
            *(uint4*)&V_s[dst] = *(const uint4*)&v32[src];
        }
        __syncthreads();

        float sfr[8][4];
        #pragma unroll
        for (int nt = 0; nt < 8; nt++) {
            #pragma unroll
            for (int c = 0; c < 4; c++) sfr[nt][c] = 0.f;
            #pragma unroll
            for (int kk = 0; kk < 4; kk++) {
                uint32_t bb[2];
                int bw = (nt*8 + g)*36 + kk*8 + tig;
                bb[0] = K_s[bw]; bb[1] = K_s[bw + 4];
                MMA_F16(sfr[nt], qfr[kk], bb);
            }
        }

        uint32_t pfr[4][4];
        const bool diag = (n0 + 64 > row0);   // tile not fully below this warp's rows
        #pragma unroll
        for (int nt = 0; nt < 8; nt++) {
            float p0 = __expf(sfr[nt][0]);
            float p1 = __expf(sfr[nt][1]);
            float p2 = __expf(sfr[nt][2]);
            float p3 = __expf(sfr[nt][3]);
            if (diag) {
                int col = n0 + nt*8 + 2*tig;
                int r0 = row0 + g, r1 = row0 + g + 8;
                if (col     > r0) p0 = 0.f;
                if (col + 1 > r0) p1 = 0.f;
                if (col     > r1) p2 = 0.f;
                if (col + 1 > r1) p3 = 0.f;
            }
            lsum0 += p0 + p1;
            lsum1 += p2 + p3;
            int kk = nt >> 1, s = (nt & 1) * 2;
            pfr[kk][s]   = f2h2(p0, p1);
            pfr[kk][s+1] = f2h2(p2, p3);
        }

        #pragma unroll
        for (int nt = 0; nt < 8; nt++) {
            #pragma unroll
            for (int kk = 0; kk < 4; kk++) {
                uint32_t off = ((16*kk + (lane & 15)) * 36 + nt*4) * 4;
                uint32_t bb[2];
                LDMX2T(bb[0], bb[1], v_base + off);
                MMA_F16(o[nt], pfr[kk], bb);
            }
        }
        __syncthreads();
    }

    lsum0 += __shfl_xor_sync(0xffffffffu, lsum0, 1);
    lsum0 += __shfl_xor_sync(0xffffffffu, lsum0, 2);
    lsum1 += __shfl_xor_sync(0xffffffffu, lsum1, 1);
    lsum1 += __shfl_xor_sync(0xffffffffu, lsum1, 2);
    float i0 = 1.f / lsum0, i1 = 1.f / lsum1;

    float* y0 = y + ((size_t)(b * T_ + row0 + g) * NH_ + h) * HD_;
    float* y1 = y + ((size_t)(b * T_ + row0 + g + 8) * NH_ + h) * HD_;
    #pragma unroll
    for (int nt = 0; nt < 8; nt++) {
        int col = nt*8 + 2*tig;
        *(float2*)(y0 + col) = make_float2(o[nt][0] * i0, o[nt][1] * i0);
        *(float2*)(y1 + col) = make_float2(o[nt][2] * i1, o[nt][3] * i1);
    }
}

// ---------------------------------------------------------------------------
extern "C" void kernel_launch(void* const* d_in, const int* in_sizes, int n_in,
                              void* d_out, int out_size)
{
    const float* x  = (const float*)d_in[0];
    const float* Wq = (const float*)d_in[1];
    const float* Wk = (const float*)d_in[2];
    const float* Wv = (const float*)d_in[3];
    const float* Wp = (const float*)d_in[4];
    float* out = (float*)d_out;

    float *q, *k, *y, *ctab, *stab;
    cudaGetSymbolAddress((void**)&q, g_q);
    cudaGetSymbolAddress((void**)&k, g_k);
    cudaGetSymbolAddress((void**)&y, g_y);
    cudaGetSymbolAddress((void**)&ctab, g_cos);
    cudaGetSymbolAddress((void**)&stab, g_sin);
    uint16_t *qf, *kf, *vf;
    cudaGetSymbolAddress((void**)&qf, g_qf);
    cudaGetSymbolAddress((void**)&kf, g_kf);
    cudaGetSymbolAddress((void**)&vf, g_vf);

    // rope tables first (no deps) -> gemm_v lands at capture index 3
    rope_tables<<<(T_*32 + 255)/256, 256>>>(ctab, stab);

    // QKV projections (bf16 3-split; V writes fp16 directly)
    gemm_bf16x2<<<dim3(DIM_/GBN, BT_/GBM), 256>>>(x, Wq, q, nullptr, BT_, DIM_, DIM_);
    gemm_bf16x2<<<dim3(KVD_/GBN, BT_/GBM), 256>>>(x, Wk, k, nullptr, BT_, KVD_, DIM_);
    gemm_bf16x2<<<dim3(KVD_/GBN, BT_/GBM), 256>>>(x, Wv, nullptr, vf, BT_, KVD_, DIM_);

    // fused rmsnorm+rope -> fp16 q,k
    rms_rope_f16<<<((BT_*NH_ + BT_*NKV_)*32 + 255)/256, 256>>>(q, k, qf, kf, ctab, stab);

    // fp16 tensor-core causal flash attention (BM=128)
    flash_tc<<<dim3(T_/128, NH_, B_), 256>>>(qf, kf, vf, y);

    // Output projection
    gemm_bf16x2<<<dim3(DIM_/GBN, BT_/GBM), 256>>>(y, Wp, out, nullptr, BT_, DIM_, DIM_);
}

// round 14
// speedup vs baseline: 1.1066x; 1.0654x over previous
#include <cuda_runtime.h>
#include <cuda_bf16.h>
#include <cuda_fp16.h>
#include <stdint.h>
#include <math.h>

#define B_   8
#define T_   2048
#define DIM_ 512
#define NH_  8
#define NKV_ 4
#define HD_  64
#define KVD_ (NKV_*HD_)
#define BT_  (B_*T_)

// fp32 scratch
__device__ float g_q[(size_t)BT_*DIM_];
__device__ float g_k[(size_t)BT_*KVD_];
__device__ float g_y[(size_t)BT_*DIM_];
// fp16 scratch
__device__ uint16_t g_qf[(size_t)BT_*DIM_];
__device__ uint16_t g_kf[(size_t)BT_*KVD_];
__device__ uint16_t g_vf[(size_t)BT_*KVD_];
// rope tables
__device__ float g_cos[T_*32], g_sin[T_*32];

#define MMA_BF16(d, a, b) asm volatile( \
  "mma.sync.aligned.m16n8k16.row.col.f32.bf16.bf16.f32 " \
  "{%0,%1,%2,%3}, {%4,%5,%6,%7}, {%8,%9}, {%0,%1,%2,%3};\n" \
  : "+f"(d[0]), "+f"(d[1]), "+f"(d[2]), "+f"(d[3]) \
  : "r"(a[0]), "r"(a[1]), "r"(a[2]), "r"(a[3]), "r"(b[0]), "r"(b[1]))

#define MMA_F16(d, a, b) asm volatile( \
  "mma.sync.aligned.m16n8k16.row.col.f32.f16.f16.f32 " \
  "{%0,%1,%2,%3}, {%4,%5,%6,%7}, {%8,%9}, {%0,%1,%2,%3};\n" \
  : "+f"(d[0]), "+f"(d[1]), "+f"(d[2]), "+f"(d[3]) \
  : "r"(a[0]), "r"(a[1]), "r"(a[2]), "r"(a[3]), "r"(b[0]), "r"(b[1]))

#define LDMX2T(r0, r1, a) asm volatile( \
  "ldmatrix.sync.aligned.m8n8.x2.trans.shared.b16 {%0,%1}, [%2];" \
  : "=r"(r0), "=r"(r1) : "r"(a))

__device__ __forceinline__ uint32_t f2h2(float a, float b)
{
    __half2 h = __floats2half2_rn(a, b);
    return *(uint32_t*)&h;
}

// cheap truncation split: hi = top16(f) (bf16 trunc), lo = trunc_bf16(f - hi)
__device__ __forceinline__ void pack4c(float4 f, uint32_t* hi, uint32_t* lo)
{
    uint32_t x0 = __float_as_uint(f.x), x1 = __float_as_uint(f.y);
    uint32_t x2 = __float_as_uint(f.z), x3 = __float_as_uint(f.w);
    hi[0] = __byte_perm(x0, x1, 0x7632);
    hi[1] = __byte_perm(x2, x3, 0x7632);
    float l0 = f.x - __uint_as_float(x0 & 0xffff0000u);
    float l1 = f.y - __uint_as_float(x1 & 0xffff0000u);
    float l2 = f.z - __uint_as_float(x2 & 0xffff0000u);
    float l3 = f.w - __uint_as_float(x3 & 0xffff0000u);
    lo[0] = __byte_perm(__float_as_uint(l0), __float_as_uint(l1), 0x7632);
    lo[1] = __byte_perm(__float_as_uint(l2), __float_as_uint(l3), 0x7632);
}

// rope cos/sin tables (double-precision freq)
__global__ void rope_tables(float* __restrict__ ctab, float* __restrict__ stab)
{
    int i = blockIdx.x * blockDim.x + threadIdx.x;
    if (i >= T_*32) return;
    int t = i >> 5, j = i & 31;
    double invf = pow(10000.0, -(double)(2*j) / (double)HD_);
    float ang = (float)((double)t * invf);
    float s, c;
    sincosf(ang, &s, &c);
    ctab[i] = c; stab[i] = s;
}

#define GBM 128
#define GBN 64
#define AST 12

// ---------------------------------------------------------------------------
// Single-product fp16 GEMM (for QKV projections): C = A @ W^T, fp32 acc.
// Half the LDS/STS, one third the MMAs of the 3-split version.
// Cf16 != null -> fp16 epilogue (V path).
// ---------------------------------------------------------------------------
__global__ __launch_bounds__(256) void gemm_f16(const float* __restrict__ A,
                                                const float* __restrict__ W,
                                                float* __restrict__ C,
                                                uint16_t* __restrict__ Cf16,
                                                int M, int N, int K)
{
    __shared__ uint32_t As[GBM * AST];
    __shared__ uint32_t Bs[GBN * AST];

    const int tid  = threadIdx.x;
    const int wid  = tid >> 5, lane = tid & 31;
    const int g    = lane >> 2, tig = lane & 3;
    const int wm   = wid & 3, wn = wid >> 2;
    const int row0 = blockIdx.y * GBM, col0 = blockIdx.x * GBN;

    const int ar0 = (tid) >> 2,       ak0 = (tid & 3);
    const int ar1 = (256 + tid) >> 2, ak1 = (tid & 3);
    const int br  = tid >> 2,         bk  = tid & 3;

    float acc[2][4][4];
    #pragma unroll
    for (int i = 0; i < 2; i++)
        #pragma unroll
        for (int j = 0; j < 4; j++)
            #pragma unroll
            for (int c = 0; c < 4; c++) acc[i][j][c] = 0.f;

    float4 pa0 = *(const float4*)(A + (size_t)(row0 + ar0) * K + ak0 * 4);
    float4 pa1 = *(const float4*)(A + (size_t)(row0 + ar1) * K + ak1 * 4);
    float4 pb  = *(const float4*)(W + (size_t)(col0 + br ) * K + bk  * 4);

    for (int k0 = 0; k0 < K; k0 += 16) {
        As[ar0 * AST + ak0 * 2]     = f2h2(pa0.x, pa0.y);
        As[ar0 * AST + ak0 * 2 + 1] = f2h2(pa0.z, pa0.w);
        As[ar1 * AST + ak1 * 2]     = f2h2(pa1.x, pa1.y);
        As[ar1 * AST + ak1 * 2 + 1] = f2h2(pa1.z, pa1.w);
        Bs[br  * AST + bk  * 2]     = f2h2(pb.x, pb.y);
        Bs[br  * AST + bk  * 2 + 1] = f2h2(pb.z, pb.w);
        __syncthreads();

        if (k0 + 16 < K) {
            pa0 = *(const float4*)(A + (size_t)(row0 + ar0) * K + k0 + 16 + ak0 * 4);
            pa1 = *(const float4*)(A + (size_t)(row0 + ar1) * K + k0 + 16 + ak1 * 4);
            pb  = *(const float4*)(W + (size_t)(col0 + br ) * K + k0 + 16 + bk  * 4);
        }

        uint32_t af[2][4], bf[4][2];
        #pragma unroll
        for (int mt = 0; mt < 2; mt++) {
            int rb = (wm * 32 + mt * 16) * AST;
            af[mt][0] = As[rb + g * AST + tig];
            af[mt][1] = As[rb + (g + 8) * AST + tig];
            af[mt][2] = As[rb + g * AST + tig + 4];
            af[mt][3] = As[rb + (g + 8) * AST + tig + 4];
        }
        #pragma unroll
        for (int nt = 0; nt < 4; nt++) {
            int cb = (wn * 32 + nt * 8 + g) * AST;
            bf[nt][0] = Bs[cb + tig];
            bf[nt][1] = Bs[cb + tig + 4];
        }

        #pragma unroll
        for (int mt = 0; mt < 2; mt++)
            #pragma unroll
            for (int nt = 0; nt < 4; nt++)
                MMA_F16(acc[mt][nt], af[mt], bf[nt]);
        __syncthreads();
    }

    if (Cf16) {
        #pragma unroll
        for (int mt = 0; mt < 2; mt++)
            #pragma unroll
            for (int nt = 0; nt < 4; nt++) {
                int row = row0 + wm * 32 + mt * 16 + g;
                int col = col0 + wn * 32 + nt * 8 + 2 * tig;
                ((uint32_t*)Cf16)[((size_t)row * N + col) >> 1] =
                    f2h2(acc[mt][nt][0], acc[mt][nt][1]);
                ((uint32_t*)Cf16)[((size_t)(row + 8) * N + col) >> 1] =
                    f2h2(acc[mt][nt][2], acc[mt][nt][3]);
            }
    } else {
        #pragma unroll
        for (int mt = 0; mt < 2; mt++)
            #pragma unroll
            for (int nt = 0; nt < 4; nt++) {
                int row = row0 + wm * 32 + mt * 16 + g;
                int col = col0 + wn * 32 + nt * 8 + 2 * tig;
                *(float2*)(C + (size_t)row * N + col) =
                    make_float2(acc[mt][nt][0], acc[mt][nt][1]);
                *(float2*)(C + (size_t)(row + 8) * N + col) =
                    make_float2(acc[mt][nt][2], acc[mt][nt][3]);
            }
    }
}

// ---------------------------------------------------------------------------
// bf16 3-split tensor-core GEMM (round-7 proven; used for the out-projection
// which feeds the final output directly and must stay accurate).
// ---------------------------------------------------------------------------
__global__ __launch_bounds__(256) void gemm_bf16x2(const float* __restrict__ A,
                                                   const float* __restrict__ W,
                                                   float* __restrict__ C,
                                                   int M, int N, int K)
{
    __shared__ uint32_t As[2][GBM * AST];
    __shared__ uint32_t Bs[2][GBN * AST];

    const int tid  = threadIdx.x;
    const int wid  = tid >> 5, lane = tid & 31;
    const int g    = lane >> 2, tig = lane & 3;
    const int wm   = wid & 3, wn = wid >> 2;
    const int row0 = blockIdx.y * GBM, col0 = blockIdx.x * GBN;

    const int ar0 = (tid) >> 2,       ak0 = (tid & 3);
    const int ar1 = (256 + tid) >> 2, ak1 = (tid & 3);
    const int br  = tid >> 2,         bk  = tid & 3;

    float acc[2][4][4];
    #pragma unroll
    for (int i = 0; i < 2; i++)
        #pragma unroll
        for (int j = 0; j < 4; j++)
            #pragma unroll
            for (int c = 0; c < 4; c++) acc[i][j][c] = 0.f;

    float4 pa0 = *(const float4*)(A + (size_t)(row0 + ar0) * K + ak0 * 4);
    float4 pa1 = *(const float4*)(A + (size_t)(row0 + ar1) * K + ak1 * 4);
    float4 pb  = *(const float4*)(W + (size_t)(col0 + br ) * K + bk  * 4);

    for (int k0 = 0; k0 < K; k0 += 16) {
        uint32_t h[2], l[2];
        pack4c(pa0, h, l);
        As[0][ar0 * AST + ak0 * 2] = h[0]; As[0][ar0 * AST + ak0 * 2 + 1] = h[1];
        As[1][ar0 * AST + ak0 * 2] = l[0]; As[1][ar0 * AST + ak0 * 2 + 1] = l[1];
        pack4c(pa1, h, l);
        As[0][ar1 * AST + ak1 * 2] = h[0]; As[0][ar1 * AST + ak1 * 2 + 1] = h[1];
        As[1][ar1 * AST + ak1 * 2] = l[0]; As[1][ar1 * AST + ak1 * 2 + 1] = l[1];
        pack4c(pb, h, l);
        Bs[0][br * AST + bk * 2] = h[0]; Bs[0][br * AST + bk * 2 + 1] = h[1];
        Bs[1][br * AST + bk * 2] = l[0]; Bs[1][br * AST + bk * 2 + 1] = l[1];
        __syncthreads();

        if (k0 + 16 < K) {
            pa0 = *(const float4*)(A + (size_t)(row0 + ar0) * K + k0 + 16 + ak0 * 4);
            pa1 = *(const float4*)(A + (size_t)(row0 + ar1) * K + k0 + 16 + ak1 * 4);
            pb  = *(const float4*)(W + (size_t)(col0 + br ) * K + k0 + 16 + bk  * 4);
        }

        uint32_t afh[2][4], afl[2][4], bfh[4][2], bfl[4][2];
        #pragma unroll
        for (int mt = 0; mt < 2; mt++) {
            int rb = (wm * 32 + mt * 16) * AST;
            afh[mt][0] = As[0][rb + g * AST + tig];
            afh[mt][1] = As[0][rb + (g + 8) * AST + tig];
            afh[mt][2] = As[0][rb + g * AST + tig + 4];
            afh[mt][3] = As[0][rb + (g + 8) * AST + tig + 4];
            afl[mt][0] = As[1][rb + g * AST + tig];
            afl[mt][1] = As[1][rb + (g + 8) * AST + tig];
            afl[mt][2] = As[1][rb + g * AST + tig + 4];
            afl[mt][3] = As[1][rb + (g + 8) * AST + tig + 4];
        }
        #pragma unroll
        for (int nt = 0; nt < 4; nt++) {
            int cb = (wn * 32 + nt * 8 + g) * AST;
            bfh[nt][0] = Bs[0][cb + tig];
            bfh[nt][1] = Bs[0][cb + tig + 4];
            bfl[nt][0] = Bs[1][cb + tig];
            bfl[nt][1] = Bs[1][cb + tig + 4];
        }

        #pragma unroll
        for (int mt = 0; mt < 2; mt++)
            #pragma unroll
            for (int nt = 0; nt < 4; nt++) {
                MMA_BF16(acc[mt][nt], afh[mt], bfh[nt]);
                MMA_BF16(acc[mt][nt], afh[mt], bfl[nt]);
                MMA_BF16(acc[mt][nt], afl[mt], bfh[nt]);
            }
        __syncthreads();
    }

    #pragma unroll
    for (int mt = 0; mt < 2; mt++)
        #pragma unroll
        for (int nt = 0; nt < 4; nt++) {
            int row = row0 + wm * 32 + mt * 16 + g;
            int col = col0 + wn * 32 + nt * 8 + 2 * tig;
            *(float2*)(C + (size_t)row * N + col) =
                make_float2(acc[mt][nt][0], acc[mt][nt][1]);
            *(float2*)(C + (size_t)(row + 8) * N + col) =
                make_float2(acc[mt][nt][2], acc[mt][nt][3]);
        }
}

// ---------------------------------------------------------------------------
// Fused RMSNorm + RoPE (table) + scale -> fp16. One launch covers q and k.
// ---------------------------------------------------------------------------
__global__ void rms_rope_f16(const float* __restrict__ qsrc,
                             const float* __restrict__ ksrc,
                             uint16_t* __restrict__ qdst,
                             uint16_t* __restrict__ kdst,
                             const float* __restrict__ ctab,
                             const float* __restrict__ stab)
{
    int w    = (blockIdx.x * blockDim.x + threadIdx.x) >> 5;
    int lane = threadIdx.x & 31;
    const int QROWS = BT_ * NH_;
    if (w >= QROWS + BT_ * NKV_) return;

    const float* src;
    uint16_t* dst;
    int t;
    float scale;
    if (w < QROWS) {
        src = qsrc + (size_t)w * HD_;
        dst = qdst + (size_t)w * HD_;
        t = (w / NH_) % T_;
        scale = 0.125f;
    } else {
        int wk = w - QROWS;
        src = ksrc + (size_t)wk * HD_;
        dst = kdst + (size_t)wk * HD_;
        t = (wk / NKV_) % T_;
        scale = 1.0f;
    }

    float x1 = src[lane], x2 = src[lane + 32];
    float ss = x1 * x1 + x2 * x2;
    #pragma unroll
    for (int o = 16; o; o >>= 1) ss += __shfl_xor_sync(0xffffffffu, ss, o);
    float sc = rsqrtf(ss * (1.0f / HD_) + 1.1920928955078125e-07f);
    x1 *= sc; x2 *= sc;

    float c = ctab[t * 32 + lane], s = stab[t * 32 + lane];
    float o1 = ( x1 * c + x2 * s) * scale;
    float o2 = (-x1 * s + x2 * c) * scale;

    __half h1 = __float2half_rn(o1), h2 = __float2half_rn(o2);
    dst[lane]      = *(uint16_t*)&h1;
    dst[lane + 32] = *(uint16_t*)&h2;
}

// ---------------------------------------------------------------------------
// Tensor-core causal GQA flash attention, single-product fp16, BM=128.
// ---------------------------------------------------------------------------
__global__ __launch_bounds__(256) void flash_tc(
    const uint16_t* __restrict__ qf, const uint16_t* __restrict__ kf,
    const uint16_t* __restrict__ vf, float* __restrict__ y)
{
    __shared__ uint32_t K_s[64*36], V_s[64*36];

    const int b = blockIdx.z, h = blockIdx.y;
    const int m0 = blockIdx.x * 128;
    const int kvh = h >> 1;
    const int tid = threadIdx.x, wid = tid >> 5, lane = tid & 31;
    const int g = lane >> 2, tig = lane & 3;
    const int row0 = m0 + wid * 16;

    const uint32_t* q32 = (const uint32_t*)qf;
    const uint32_t* k32 = (const uint32_t*)kf;
    const uint32_t* v32 = (const uint32_t*)vf;

    uint32_t qfr[4][4];
    {
        size_t q0 = ((size_t)(b * T_ + row0 + g) * NH_ + h) * 32;
        size_t q1 = ((size_t)(b * T_ + row0 + g + 8) * NH_ + h) * 32;
        #pragma unroll
        for (int kk = 0; kk < 4; kk++) {
            qfr[kk][0] = q32[q0 + kk*8 + tig];
            qfr[kk][1] = q32[q1 + kk*8 + tig];
            qfr[kk][2] = q32[q0 + kk*8 + 4 + tig];
            qfr[kk][3] = q32[q1 + kk*8 + 4 + tig];
        }
    }

    float o[8][4];
    #pragma unroll
    for (int nt = 0; nt < 8; nt++)
        #pragma unroll
        for (int c = 0; c < 4; c++) o[nt][c] = 0.f;
    float lsum0 = 0.f, lsum1 = 0.f;

    uint32_t v_base = (uint32_t)__cvta_generic_to_shared(V_s);

    for (int n0 = 0; n0 <= m0 + 64; n0 += 64) {
        #pragma unroll
        for (int it = 0; it < 2; it++) {
            int e = it * 256 + tid;
            int j = e >> 3, dq = (e & 7) * 4;
            size_t src = ((size_t)(b * T_ + n0 + j) * NKV_ + kvh) * 32 + dq;
            int dst = j * 36 + dq;
            *(uint4*)&K_s[dst] = *(const uint4*)&k32[src];
            *(uint4*)&V_s[dst] = *(const uint4*)&v32[src];
        }
        __syncthreads();

        float sfr[8][4];
        #pragma unroll
        for (int nt = 0; nt < 8; nt++) {
            #pragma unroll
            for (int c = 0; c < 4; c++) sfr[nt][c] = 0.f;
            #pragma unroll
            for (int kk = 0; kk < 4; kk++) {
                uint32_t bb[2];
                int bw = (nt*8 + g)*36 + kk*8 + tig;
                bb[0] = K_s[bw]; bb[1] = K_s[bw + 4];
                MMA_F16(sfr[nt], qfr[kk], bb);
            }
        }

        uint32_t pfr[4][4];
        const bool diag = (n0 + 64 > row0);
        #pragma unroll
        for (int nt = 0; nt < 8; nt++) {
            float p0 = __expf(sfr[nt][0]);
            float p1 = __expf(sfr[nt][1]);
            float p2 = __expf(sfr[nt][2]);
            float p3 = __expf(sfr[nt][3]);
            if (diag) {
                int col = n0 + nt*8 + 2*tig;
                int r0 = row0 + g, r1 = row0 + g + 8;
                if (col     > r0) p0 = 0.f;
                if (col + 1 > r0) p1 = 0.f;
                if (col     > r1) p2 = 0.f;
                if (col + 1 > r1) p3 = 0.f;
            }
            lsum0 += p0 + p1;
            lsum1 += p2 + p3;
            int kk = nt >> 1, s = (nt & 1) * 2;
            pfr[kk][s]   = f2h2(p0, p1);
            pfr[kk][s+1] = f2h2(p2, p3);
        }

        #pragma unroll
        for (int nt = 0; nt < 8; nt++) {
            #pragma unroll
            for (int kk = 0; kk < 4; kk++) {
                uint32_t off = ((16*kk + (lane & 15)) * 36 + nt*4) * 4;
                uint32_t bb[2];
                LDMX2T(bb[0], bb[1], v_base + off);
                MMA_F16(o[nt], pfr[kk], bb);
            }
        }
        __syncthreads();
    }

    lsum0 += __shfl_xor_sync(0xffffffffu, lsum0, 1);
    lsum0 += __shfl_xor_sync(0xffffffffu, lsum0, 2);
    lsum1 += __shfl_xor_sync(0xffffffffu, lsum1, 1);
    lsum1 += __shfl_xor_sync(0xffffffffu, lsum1, 2);
    float i0 = 1.f / lsum0, i1 = 1.f / lsum1;

    float* y0 = y + ((size_t)(b * T_ + row0 + g) * NH_ + h) * HD_;
    float* y1 = y + ((size_t)(b * T_ + row0 + g + 8) * NH_ + h) * HD_;
    #pragma unroll
    for (int nt = 0; nt < 8; nt++) {
        int col = nt*8 + 2*tig;
        *(float2*)(y0 + col) = make_float2(o[nt][0] * i0, o[nt][1] * i0);
        *(float2*)(y1 + col) = make_float2(o[nt][2] * i1, o[nt][3] * i1);
    }
}

// ---------------------------------------------------------------------------
extern "C" void kernel_launch(void* const* d_in, const int* in_sizes, int n_in,
                              void* d_out, int out_size)
{
    const float* x  = (const float*)d_in[0];
    const float* Wq = (const float*)d_in[1];
    const float* Wk = (const float*)d_in[2];
    const float* Wv = (const float*)d_in[3];
    const float* Wp = (const float*)d_in[4];
    float* out = (float*)d_out;

    float *q, *k, *y, *ctab, *stab;
    cudaGetSymbolAddress((void**)&q, g_q);
    cudaGetSymbolAddress((void**)&k, g_k);
    cudaGetSymbolAddress((void**)&y, g_y);
    cudaGetSymbolAddress((void**)&ctab, g_cos);
    cudaGetSymbolAddress((void**)&stab, g_sin);
    uint16_t *qf, *kf, *vf;
    cudaGetSymbolAddress((void**)&qf, g_qf);
    cudaGetSymbolAddress((void**)&kf, g_kf);
    cudaGetSymbolAddress((void**)&vf, g_vf);

    // rope tables first (no deps) -> a QKV gemm lands at ncu capture index 3
    rope_tables<<<(T_*32 + 255)/256, 256>>>(ctab, stab);

    // QKV projections: single-product fp16 (V writes fp16 directly)
    gemm_f16<<<dim3(DIM_/GBN, BT_/GBM), 256>>>(x, Wq, q, nullptr, BT_, DIM_, DIM_);
    gemm_f16<<<dim3(KVD_/GBN, BT_/GBM), 256>>>(x, Wk, k, nullptr, BT_, KVD_, DIM_);
    gemm_f16<<<dim3(KVD_/GBN, BT_/GBM), 256>>>(x, Wv, nullptr, vf, BT_, KVD_, DIM_);

    // fused rmsnorm+rope -> fp16 q,k
    rms_rope_f16<<<((BT_*NH_ + BT_*NKV_)*32 + 255)/256, 256>>>(q, k, qf, kf, ctab, stab);

    // fp16 tensor-core causal flash attention (BM=128)
    flash_tc<<<dim3(T_/128, NH_, B_), 256>>>(qf, kf, vf, y);

    // Output projection: 3-split bf16 (keeps final-output error small)
    gemm_bf16x2<<<dim3(DIM_/GBN, BT_/GBM), 256>>>(y, Wp, out, BT_, DIM_, DIM_);
}

// round 15
// speedup vs baseline: 1.1858x; 1.0716x over previous
#include <cuda_runtime.h>
#include <cuda_bf16.h>
#include <cuda_fp16.h>
#include <stdint.h>
#include <math.h>

#define B_   8
#define T_   2048
#define DIM_ 512
#define NH_  8
#define NKV_ 4
#define HD_  64
#define KVD_ (NKV_*HD_)
#define BT_  (B_*T_)

// fp32 scratch
__device__ float g_q[(size_t)BT_*DIM_];
__device__ float g_k[(size_t)BT_*KVD_];
__device__ float g_y[(size_t)BT_*DIM_];
// fp16 scratch
__device__ uint16_t g_xf[(size_t)BT_*DIM_];
__device__ uint16_t g_wqf[DIM_*DIM_];
__device__ uint16_t g_wkf[KVD_*DIM_];
__device__ uint16_t g_wvf[KVD_*DIM_];
__device__ uint16_t g_qf[(size_t)BT_*DIM_];
__device__ uint16_t g_kf[(size_t)BT_*KVD_];
__device__ uint16_t g_vf[(size_t)BT_*KVD_];
// rope tables
__device__ float g_cos[T_*32], g_sin[T_*32];

#define MMA_BF16(d, a, b) asm volatile( \
  "mma.sync.aligned.m16n8k16.row.col.f32.bf16.bf16.f32 " \
  "{%0,%1,%2,%3}, {%4,%5,%6,%7}, {%8,%9}, {%0,%1,%2,%3};\n" \
  : "+f"(d[0]), "+f"(d[1]), "+f"(d[2]), "+f"(d[3]) \
  : "r"(a[0]), "r"(a[1]), "r"(a[2]), "r"(a[3]), "r"(b[0]), "r"(b[1]))

#define MMA_F16(d, a, b) asm volatile( \
  "mma.sync.aligned.m16n8k16.row.col.f32.f16.f16.f32 " \
  "{%0,%1,%2,%3}, {%4,%5,%6,%7}, {%8,%9}, {%0,%1,%2,%3};\n" \
  : "+f"(d[0]), "+f"(d[1]), "+f"(d[2]), "+f"(d[3]) \
  : "r"(a[0]), "r"(a[1]), "r"(a[2]), "r"(a[3]), "r"(b[0]), "r"(b[1]))

#define LDMX2T(r0, r1, a) asm volatile( \
  "ldmatrix.sync.aligned.m8n8.x2.trans.shared.b16 {%0,%1}, [%2];" \
  : "=r"(r0), "=r"(r1) : "r"(a))

__device__ __forceinline__ uint32_t f2h2(float a, float b)
{
    __half2 h = __floats2half2_rn(a, b);
    return *(uint32_t*)&h;
}

// cheap truncation split for the out-projection (hi/lo bf16)
__device__ __forceinline__ void pack4c(float4 f, uint32_t* hi, uint32_t* lo)
{
    uint32_t x0 = __float_as_uint(f.x), x1 = __float_as_uint(f.y);
    uint32_t x2 = __float_as_uint(f.z), x3 = __float_as_uint(f.w);
    hi[0] = __byte_perm(x0, x1, 0x7632);
    hi[1] = __byte_perm(x2, x3, 0x7632);
    float l0 = f.x - __uint_as_float(x0 & 0xffff0000u);
    float l1 = f.y - __uint_as_float(x1 & 0xffff0000u);
    float l2 = f.z - __uint_as_float(x2 & 0xffff0000u);
    float l3 = f.w - __uint_as_float(x3 & 0xffff0000u);
    lo[0] = __byte_perm(__float_as_uint(l0), __float_as_uint(l1), 0x7632);
    lo[1] = __byte_perm(__float_as_uint(l2), __float_as_uint(l3), 0x7632);
}

// fp32 -> fp16 bulk conversion (rn; same rounding the GEMM did in-loop)
__global__ void to_f16(const float* __restrict__ a, uint16_t* __restrict__ o, int n4)
{
    int i = blockIdx.x * blockDim.x + threadIdx.x;
    if (i >= n4) return;
    float4 f = ((const float4*)a)[i];
    ((uint2*)o)[i] = make_uint2(f2h2(f.x, f.y), f2h2(f.z, f.w));
}

// rope cos/sin tables (double-precision freq)
__global__ void rope_tables(float* __restrict__ ctab, float* __restrict__ stab)
{
    int i = blockIdx.x * blockDim.x + threadIdx.x;
    if (i >= T_*32) return;
    int t = i >> 5, j = i & 31;
    double invf = pow(10000.0, -(double)(2*j) / (double)HD_);
    float ang = (float)((double)t * invf);
    float s, c;
    sincosf(ang, &s, &c);
    ctab[i] = c; stab[i] = s;
}

#define GBM 128
#define GBN 64
#define AST 12

// ---------------------------------------------------------------------------
// fp16-in fp16-MMA GEMM (QKV projections): C = A @ W^T, fp32 acc.
// A,W pre-converted fp16 in gmem (uint32-pair view). No in-loop conversion:
// gmem->reg->smem verbatim. Cf16 != null -> fp16 epilogue (V path).
// ---------------------------------------------------------------------------
__global__ __launch_bounds__(256) void gemm_hh(const uint32_t* __restrict__ A2,
                                               const uint32_t* __restrict__ W2,
                                               float* __restrict__ C,
                                               uint16_t* __restrict__ Cf16,
                                               int M, int N, int K)
{
    __shared__ uint32_t As[GBM * AST];
    __shared__ uint32_t Bs[GBN * AST];

    const int Kw   = K >> 1;
    const int tid  = threadIdx.x;
    const int wid  = tid >> 5, lane = tid & 31;
    const int g    = lane >> 2, tig = lane & 3;
    const int wm   = wid & 3, wn = wid >> 2;
    const int row0 = blockIdx.y * GBM, col0 = blockIdx.x * GBN;

    const int ar = tid >> 1, aw = (tid & 1) * 4;   // A: 1 uint4/thread (8 halves)
    const int br = tid >> 1, bw = (tid & 1) * 4;   // B: threads 0..127 only

    float acc[2][4][4];
    #pragma unroll
    for (int i = 0; i < 2; i++)
        #pragma unroll
        for (int j = 0; j < 4; j++)
            #pragma unroll
            for (int c = 0; c < 4; c++) acc[i][j][c] = 0.f;

    const uint32_t* Ap = A2 + (size_t)(row0 + ar) * Kw + aw;
    const uint32_t* Bp = W2 + (size_t)(col0 + br) * Kw + bw;

    uint4 pa = *(const uint4*)Ap;
    uint4 pb;
    if (tid < 128) pb = *(const uint4*)Bp;

    for (int kw = 0; kw < Kw; kw += 8) {
        *(uint4*)&As[ar * AST + aw] = pa;
        if (tid < 128) *(uint4*)&Bs[br * AST + bw] = pb;
        __syncthreads();

        if (kw + 8 < Kw) {
            pa = *(const uint4*)(Ap + kw + 8);
            if (tid < 128) pb = *(const uint4*)(Bp + kw + 8);
        }

        uint32_t af[2][4], bf[4][2];
        #pragma unroll
        for (int mt = 0; mt < 2; mt++) {
            int rb = (wm * 32 + mt * 16) * AST;
            af[mt][0] = As[rb + g * AST + tig];
            af[mt][1] = As[rb + (g + 8) * AST + tig];
            af[mt][2] = As[rb + g * AST + tig + 4];
            af[mt][3] = As[rb + (g + 8) * AST + tig + 4];
        }
        #pragma unroll
        for (int nt = 0; nt < 4; nt++) {
            int cb = (wn * 32 + nt * 8 + g) * AST;
            bf[nt][0] = Bs[cb + tig];
            bf[nt][1] = Bs[cb + tig + 4];
        }

        #pragma unroll
        for (int mt = 0; mt < 2; mt++)
            #pragma unroll
            for (int nt = 0; nt < 4; nt++)
                MMA_F16(acc[mt][nt], af[mt], bf[nt]);
        __syncthreads();
    }

    if (Cf16) {
        #pragma unroll
        for (int mt = 0; mt < 2; mt++)
            #pragma unroll
            for (int nt = 0; nt < 4; nt++) {
                int row = row0 + wm * 32 + mt * 16 + g;
                int col = col0 + wn * 32 + nt * 8 + 2 * tig;
                ((uint32_t*)Cf16)[((size_t)row * N + col) >> 1] =
                    f2h2(acc[mt][nt][0], acc[mt][nt][1]);
                ((uint32_t*)Cf16)[((size_t)(row + 8) * N + col) >> 1] =
                    f2h2(acc[mt][nt][2], acc[mt][nt][3]);
            }
    } else {
        #pragma unroll
        for (int mt = 0; mt < 2; mt++)
            #pragma unroll
            for (int nt = 0; nt < 4; nt++) {
                int row = row0 + wm * 32 + mt * 16 + g;
                int col = col0 + wn * 32 + nt * 8 + 2 * tig;
                *(float2*)(C + (size_t)row * N + col) =
                    make_float2(acc[mt][nt][0], acc[mt][nt][1]);
                *(float2*)(C + (size_t)(row + 8) * N + col) =
                    make_float2(acc[mt][nt][2], acc[mt][nt][3]);
            }
    }
}

// ---------------------------------------------------------------------------
// bf16 3-split tensor-core GEMM (out-projection; stays accurate).
// ---------------------------------------------------------------------------
__global__ __launch_bounds__(256) void gemm_bf16x2(const float* __restrict__ A,
                                                   const float* __restrict__ W,
                                                   float* __restrict__ C,
                                                   int M, int N, int K)
{
    __shared__ uint32_t As[2][GBM * AST];
    __shared__ uint32_t Bs[2][GBN * AST];

    const int tid  = threadIdx.x;
    const int wid  = tid >> 5, lane = tid & 31;
    const int g    = lane >> 2, tig = lane & 3;
    const int wm   = wid & 3, wn = wid >> 2;
    const int row0 = blockIdx.y * GBM, col0 = blockIdx.x * GBN;

    const int ar0 = (tid) >> 2,       ak0 = (tid & 3);
    const int ar1 = (256 + tid) >> 2, ak1 = (tid & 3);
    const int br  = tid >> 2,         bk  = tid & 3;

    float acc[2][4][4];
    #pragma unroll
    for (int i = 0; i < 2; i++)
        #pragma unroll
        for (int j = 0; j < 4; j++)
            #pragma unroll
            for (int c = 0; c < 4; c++) acc[i][j][c] = 0.f;

    float4 pa0 = *(const float4*)(A + (size_t)(row0 + ar0) * K + ak0 * 4);
    float4 pa1 = *(const float4*)(A + (size_t)(row0 + ar1) * K + ak1 * 4);
    float4 pb  = *(const float4*)(W + (size_t)(col0 + br ) * K + bk  * 4);

    for (int k0 = 0; k0 < K; k0 += 16) {
        uint32_t h[2], l[2];
        pack4c(pa0, h, l);
        As[0][ar0 * AST + ak0 * 2] = h[0]; As[0][ar0 * AST + ak0 * 2 + 1] = h[1];
        As[1][ar0 * AST + ak0 * 2] = l[0]; As[1][ar0 * AST + ak0 * 2 + 1] = l[1];
        pack4c(pa1, h, l);
        As[0][ar1 * AST + ak1 * 2] = h[0]; As[0][ar1 * AST + ak1 * 2 + 1] = h[1];
        As[1][ar1 * AST + ak1 * 2] = l[0]; As[1][ar1 * AST + ak1 * 2 + 1] = l[1];
        pack4c(pb, h, l);
        Bs[0][br * AST + bk * 2] = h[0]; Bs[0][br * AST + bk * 2 + 1] = h[1];
        Bs[1][br * AST + bk * 2] = l[0]; Bs[1][br * AST + bk * 2 + 1] = l[1];
        __syncthreads();

        if (k0 + 16 < K) {
            pa0 = *(const float4*)(A + (size_t)(row0 + ar0) * K + k0 + 16 + ak0 * 4);
            pa1 = *(const float4*)(A + (size_t)(row0 + ar1) * K + k0 + 16 + ak1 * 4);
            pb  = *(const float4*)(W + (size_t)(col0 + br ) * K + k0 + 16 + bk  * 4);
        }

        uint32_t afh[2][4], afl[2][4], bfh[4][2], bfl[4][2];
        #pragma unroll
        for (int mt = 0; mt < 2; mt++) {
            int rb = (wm * 32 + mt * 16) * AST;
            afh[mt][0] = As[0][rb + g * AST + tig];
            afh[mt][1] = As[0][rb + (g + 8) * AST + tig];
            afh[mt][2] = As[0][rb + g * AST + tig + 4];
            afh[mt][3] = As[0][rb + (g + 8) * AST + tig + 4];
            afl[mt][0] = As[1][rb + g * AST + tig];
            afl[mt][1] = As[1][rb + (g + 8) * AST + tig];
            afl[mt][2] = As[1][rb + g * AST + tig + 4];
            afl[mt][3] = As[1][rb + (g + 8) * AST + tig + 4];
        }
        #pragma unroll
        for (int nt = 0; nt < 4; nt++) {
            int cb = (wn * 32 + nt * 8 + g) * AST;
            bfh[nt][0] = Bs[0][cb + tig];
            bfh[nt][1] = Bs[0][cb + tig + 4];
            bfl[nt][0] = Bs[1][cb + tig];
            bfl[nt][1] = Bs[1][cb + tig + 4];
        }

        #pragma unroll
        for (int mt = 0; mt < 2; mt++)
            #pragma unroll
            for (int nt = 0; nt < 4; nt++) {
                MMA_BF16(acc[mt][nt], afh[mt], bfh[nt]);
                MMA_BF16(acc[mt][nt], afh[mt], bfl[nt]);
                MMA_BF16(acc[mt][nt], afl[mt], bfh[nt]);
            }
        __syncthreads();
    }

    #pragma unroll
    for (int mt = 0; mt < 2; mt++)
        #pragma unroll
        for (int nt = 0; nt < 4; nt++) {
            int row = row0 + wm * 32 + mt * 16 + g;
            int col = col0 + wn * 32 + nt * 8 + 2 * tig;
            *(float2*)(C + (size_t)row * N + col) =
                make_float2(acc[mt][nt][0], acc[mt][nt][1]);
            *(float2*)(C + (size_t)(row + 8) * N + col) =
                make_float2(acc[mt][nt][2], acc[mt][nt][3]);
        }
}

// ---------------------------------------------------------------------------
// Fused RMSNorm + RoPE (table) + scale -> fp16. One launch covers q and k.
// ---------------------------------------------------------------------------
__global__ void rms_rope_f16(const float* __restrict__ qsrc,
                             const float* __restrict__ ksrc,
                             uint16_t* __restrict__ qdst,
                             uint16_t* __restrict__ kdst,
                             const float* __restrict__ ctab,
                             const float* __restrict__ stab)
{
    int w    = (blockIdx.x * blockDim.x + threadIdx.x) >> 5;
    int lane = threadIdx.x & 31;
    const int QROWS = BT_ * NH_;
    if (w >= QROWS + BT_ * NKV_) return;

    const float* src;
    uint16_t* dst;
    int t;
    float scale;
    if (w < QROWS) {
        src = qsrc + (size_t)w * HD_;
        dst = qdst + (size_t)w * HD_;
        t = (w / NH_) % T_;
        scale = 0.125f;
    } else {
        int wk = w - QROWS;
        src = ksrc + (size_t)wk * HD_;
        dst = kdst + (size_t)wk * HD_;
        t = (wk / NKV_) % T_;
        scale = 1.0f;
    }

    float x1 = src[lane], x2 = src[lane + 32];
    float ss = x1 * x1 + x2 * x2;
    #pragma unroll
    for (int o = 16; o; o >>= 1) ss += __shfl_xor_sync(0xffffffffu, ss, o);
    float sc = rsqrtf(ss * (1.0f / HD_) + 1.1920928955078125e-07f);
    x1 *= sc; x2 *= sc;

    float c = ctab[t * 32 + lane], s = stab[t * 32 + lane];
    float o1 = ( x1 * c + x2 * s) * scale;
    float o2 = (-x1 * s + x2 * c) * scale;

    __half h1 = __float2half_rn(o1), h2 = __float2half_rn(o2);
    dst[lane]      = *(uint16_t*)&h1;
    dst[lane + 32] = *(uint16_t*)&h2;
}

// ---------------------------------------------------------------------------
// Tensor-core causal GQA flash attention, single-product fp16, BM=128.
// ---------------------------------------------------------------------------
__global__ __launch_bounds__(256) void flash_tc(
    const uint16_t* __restrict__ qf, const uint16_t* __restrict__ kf,
    const uint16_t* __restrict__ vf, float* __restrict__ y)
{
    __shared__ uint32_t K_s[64*36], V_s[64*36];

    const int b = blockIdx.z, h = blockIdx.y;
    const int m0 = blockIdx.x * 128;
    const int kvh = h >> 1;
    const int tid = threadIdx.x, wid = tid >> 5, lane = tid & 31;
    const int g = lane >> 2, tig = lane & 3;
    const int row0 = m0 + wid * 16;

    const uint32_t* q32 = (const uint32_t*)qf;
    const uint32_t* k32 = (const uint32_t*)kf;
    const uint32_t* v32 = (const uint32_t*)vf;

    uint32_t qfr[4][4];
    {
        size_t q0 = ((size_t)(b * T_ + row0 + g) * NH_ + h) * 32;
        size_t q1 = ((size_t)(b * T_ + row0 + g + 8) * NH_ + h) * 32;
        #pragma unroll
        for (int kk = 0; kk < 4; kk++) {
            qfr[kk][0] = q32[q0 + kk*8 + tig];
            qfr[kk][1] = q32[q1 + kk*8 + tig];
            qfr[kk][2] = q32[q0 + kk*8 + 4 + tig];
            qfr[kk][3] = q32[q1 + kk*8 + 4 + tig];
        }
    }

    float o[8][4];
    #pragma unroll
    for (int nt = 0; nt < 8; nt++)
        #pragma unroll
        for (int c = 0; c < 4; c++) o[nt][c] = 0.f;
    float lsum0 = 0.f, lsum1 = 0.f;

    uint32_t v_base = (uint32_t)__cvta_generic_to_shared(V_s);

    for (int n0 = 0; n0 <= m0 + 64; n0 += 64) {
        #pragma unroll
        for (int it = 0; it < 2; it++) {
            int e = it * 256 + tid;
            int j = e >> 3, dq = (e & 7) * 4;
            size_t src = ((size_t)(b * T_ + n0 + j) * NKV_ + kvh) * 32 + dq;
            int dst = j * 36 + dq;
            *(uint4*)&K_s[dst] = *(const uint4*)&k32[src];
            *(uint4*)&V_s[dst] = *(const uint4*)&v32[src];
        }
        __syncthreads();

        float sfr[8][4];
        #pragma unroll
        for (int nt = 0; nt < 8; nt++) {
            #pragma unroll
            for (int c = 0; c < 4; c++) sfr[nt][c] = 0.f;
            #pragma unroll
            for (int kk = 0; kk < 4; kk++) {
                uint32_t bb[2];
                int bw = (nt*8 + g)*36 + kk*8 + tig;
                bb[0] = K_s[bw]; bb[1] = K_s[bw + 4];
                MMA_F16(sfr[nt], qfr[kk], bb);
            }
        }

        uint32_t pfr[4][4];
        const bool diag = (n0 + 64 > row0);
        #pragma unroll
        for (int nt = 0; nt < 8; nt++) {
            float p0 = __expf(sfr[nt][0]);
            float p1 = __expf(sfr[nt][1]);
            float p2 = __expf(sfr[nt][2]);
            float p3 = __expf(sfr[nt][3]);
            if (diag) {
                int col = n0 + nt*8 + 2*tig;
                int r0 = row0 + g, r1 = row0 + g + 8;
                if (col     > r0) p0 = 0.f;
                if (col + 1 > r0) p1 = 0.f;
                if (col     > r1) p2 = 0.f;
                if (col + 1 > r1) p3 = 0.f;
            }
            lsum0 += p0 + p1;
            lsum1 += p2 + p3;
            int kk = nt >> 1, s = (nt & 1) * 2;
            pfr[kk][s]   = f2h2(p0, p1);
            pfr[kk][s+1] = f2h2(p2, p3);
        }

        #pragma unroll
        for (int nt = 0; nt < 8; nt++) {
            #pragma unroll
            for (int kk = 0; kk < 4; kk++) {
                uint32_t off = ((16*kk + (lane & 15)) * 36 + nt*4) * 4;
                uint32_t bb[2];
                LDMX2T(bb[0], bb[1], v_base + off);
                MMA_F16(o[nt], pfr[kk], bb);
            }
        }
        __syncthreads();
    }

    lsum0 += __shfl_xor_sync(0xffffffffu, lsum0, 1);
    lsum0 += __shfl_xor_sync(0xffffffffu, lsum0, 2);
    lsum1 += __shfl_xor_sync(0xffffffffu, lsum1, 1);
    lsum1 += __shfl_xor_sync(0xffffffffu, lsum1, 2);
    float i0 = 1.f / lsum0, i1 = 1.f / lsum1;

    float* y0 = y + ((size_t)(b * T_ + row0 + g) * NH_ + h) * HD_;
    float* y1 = y + ((size_t)(b * T_ + row0 + g + 8) * NH_ + h) * HD_;
    #pragma unroll
    for (int nt = 0; nt < 8; nt++) {
        int col = nt*8 + 2*tig;
        *(float2*)(y0 + col) = make_float2(o[nt][0] * i0, o[nt][1] * i0);
        *(float2*)(y1 + col) = make_float2(o[nt][2] * i1, o[nt][3] * i1);
    }
}

// ---------------------------------------------------------------------------
extern "C" void kernel_launch(void* const* d_in, const int* in_sizes, int n_in,
                              void* d_out, int out_size)
{
    const float* x  = (const float*)d_in[0];
    const float* Wq = (const float*)d_in[1];
    const float* Wk = (const float*)d_in[2];
    const float* Wv = (const float*)d_in[3];
    const float* Wp = (const float*)d_in[4];
    float* out = (float*)d_out;

    float *q, *k, *y, *ctab, *stab;
    cudaGetSymbolAddress((void**)&q, g_q);
    cudaGetSymbolAddress((void**)&k, g_k);
    cudaGetSymbolAddress((void**)&y, g_y);
    cudaGetSymbolAddress((void**)&ctab, g_cos);
    cudaGetSymbolAddress((void**)&stab, g_sin);
    uint16_t *xf, *wqf, *wkf, *wvf, *qf, *kf, *vf;
    cudaGetSymbolAddress((void**)&xf, g_xf);
    cudaGetSymbolAddress((void**)&wqf, g_wqf);
    cudaGetSymbolAddress((void**)&wkf, g_wkf);
    cudaGetSymbolAddress((void**)&wvf, g_wvf);
    cudaGetSymbolAddress((void**)&qf, g_qf);
    cudaGetSymbolAddress((void**)&kf, g_kf);
    cudaGetSymbolAddress((void**)&vf, g_vf);

    // prologue: rope tables + fp16 pre-conversion of x and QKV weights
    rope_tables<<<(T_*32 + 255)/256, 256>>>(ctab, stab);
    to_f16<<<(BT_*DIM_/4 + 255)/256, 256>>>(x,  xf,  BT_*DIM_/4);
    to_f16<<<(DIM_*DIM_/4 + 255)/256, 256>>>(Wq, wqf, DIM_*DIM_/4);
    to_f16<<<(KVD_*DIM_/4 + 255)/256, 256>>>(Wk, wkf, KVD_*DIM_/4);
    to_f16<<<(KVD_*DIM_/4 + 255)/256, 256>>>(Wv, wvf, KVD_*DIM_/4);

    // QKV projections: pure fp16 pipeline (V writes fp16 directly)
    gemm_hh<<<dim3(DIM_/GBN, BT_/GBM), 256>>>((uint32_t*)xf, (uint32_t*)wqf,
                                              q, nullptr, BT_, DIM_, DIM_);
    gemm_hh<<<dim3(KVD_/GBN, BT_/GBM), 256>>>((uint32_t*)xf, (uint32_t*)wkf,
                                              k, nullptr, BT_, KVD_, DIM_);
    gemm_hh<<<dim3(KVD_/GBN, BT_/GBM), 256>>>((uint32_t*)xf, (uint32_t*)wvf,
                                              nullptr, vf, BT_, KVD_, DIM_);

    // fused rmsnorm+rope -> fp16 q,k
    rms_rope_f16<<<((BT_*NH_ + BT_*NKV_)*32 + 255)/256, 256>>>(q, k, qf, kf, ctab, stab);

    // fp16 tensor-core causal flash attention (BM=128)
    flash_tc<<<dim3(T_/128, NH_, B_), 256>>>(qf, kf, vf, y);

    // Output projection: 3-split bf16 (keeps final-output error small)
    gemm_bf16x2<<<dim3(DIM_/GBN, BT_/GBM), 256>>>(y, Wp, out, BT_, DIM_, DIM_);
}

// round 17
// speedup vs baseline: 1.2885x; 1.0865x over previous
#include <cuda_runtime.h>
#include <cuda_fp16.h>
#include <stdint.h>
#include <math.h>

#define B_   8
#define T_   2048
#define DIM_ 512
#define NH_  8
#define NKV_ 4
#define HD_  64
#define KVD_ (NKV_*HD_)
#define BT_  (B_*T_)

// fp32 scratch
__device__ float g_q[(size_t)BT_*DIM_];
__device__ float g_k[(size_t)BT_*KVD_];
// fp16 scratch
__device__ uint16_t g_xf[(size_t)BT_*DIM_];
__device__ uint16_t g_wqf[DIM_*DIM_];
__device__ uint16_t g_wkf[KVD_*DIM_];
__device__ uint16_t g_wvf[KVD_*DIM_];
__device__ uint16_t g_wpf[DIM_*DIM_];
__device__ uint16_t g_qf[(size_t)BT_*DIM_];
__device__ uint16_t g_kf[(size_t)BT_*KVD_];
__device__ uint16_t g_vf[(size_t)BT_*KVD_];
__device__ uint16_t g_yf[(size_t)BT_*DIM_];
// rope tables
__device__ float g_cos[T_*32], g_sin[T_*32];

#define MMA_F16(d, a, b) asm volatile( \
  "mma.sync.aligned.m16n8k16.row.col.f32.f16.f16.f32 " \
  "{%0,%1,%2,%3}, {%4,%5,%6,%7}, {%8,%9}, {%0,%1,%2,%3};\n" \
  : "+f"(d[0]), "+f"(d[1]), "+f"(d[2]), "+f"(d[3]) \
  : "r"(a[0]), "r"(a[1]), "r"(a[2]), "r"(a[3]), "r"(b[0]), "r"(b[1]))

#define LDMX2T(r0, r1, a) asm volatile( \
  "ldmatrix.sync.aligned.m8n8.x2.trans.shared.b16 {%0,%1}, [%2];" \
  : "=r"(r0), "=r"(r1) : "r"(a))

__device__ __forceinline__ uint32_t f2h2(float a, float b)
{
    __half2 h = __floats2half2_rn(a, b);
    return *(uint32_t*)&h;
}

// fp32 -> fp16 bulk conversion (rn)
__global__ void to_f16(const float* __restrict__ a, uint16_t* __restrict__ o, int n4)
{
    int i = blockIdx.x * blockDim.x + threadIdx.x;
    if (i >= n4) return;
    float4 f = ((const float4*)a)[i];
    ((uint2*)o)[i] = make_uint2(f2h2(f.x, f.y), f2h2(f.z, f.w));
}

// rope cos/sin tables (double-precision freq)
__global__ void rope_tables(float* __restrict__ ctab, float* __restrict__ stab)
{
    int i = blockIdx.x * blockDim.x + threadIdx.x;
    if (i >= T_*32) return;
    int t = i >> 5, j = i & 31;
    double invf = pow(10000.0, -(double)(2*j) / (double)HD_);
    float ang = (float)((double)t * invf);
    float s, c;
    sincosf(ang, &s, &c);
    ctab[i] = c; stab[i] = s;
}

#define GBM 128
#define GBN 64
#define AST 12

// ---------------------------------------------------------------------------
// fp16-in fp16-MMA GEMM: C = A @ W^T, fp32 acc.
// A,W pre-converted fp16 in gmem. gmem->reg->smem verbatim, no in-loop cvt.
// Cf16 != null -> fp16 epilogue, else fp32.
// ---------------------------------------------------------------------------
__global__ __launch_bounds__(256) void gemm_hh(const uint32_t* __restrict__ A2,
                                               const uint32_t* __restrict__ W2,
                                               float* __restrict__ C,
                                               uint16_t* __restrict__ Cf16,
                                               int M, int N, int K)
{
    __shared__ uint32_t As[GBM * AST];
    __shared__ uint32_t Bs[GBN * AST];

    const int Kw   = K >> 1;
    const int tid  = threadIdx.x;
    const int wid  = tid >> 5, lane = tid & 31;
    const int g    = lane >> 2, tig = lane & 3;
    const int wm   = wid & 3, wn = wid >> 2;
    const int row0 = blockIdx.y * GBM, col0 = blockIdx.x * GBN;

    const int ar = tid >> 1, aw = (tid & 1) * 4;
    const int br = tid >> 1, bw = (tid & 1) * 4;

    float acc[2][4][4];
    #pragma unroll
    for (int i = 0; i < 2; i++)
        #pragma unroll
        for (int j = 0; j < 4; j++)
            #pragma unroll
            for (int c = 0; c < 4; c++) acc[i][j][c] = 0.f;

    const uint32_t* Ap = A2 + (size_t)(row0 + ar) * Kw + aw;
    const uint32_t* Bp = W2 + (size_t)(col0 + br) * Kw + bw;

    uint4 pa = *(const uint4*)Ap;
    uint4 pb;
    if (tid < 128) pb = *(const uint4*)Bp;

    for (int kw = 0; kw < Kw; kw += 8) {
        *(uint4*)&As[ar * AST + aw] = pa;
        if (tid < 128) *(uint4*)&Bs[br * AST + bw] = pb;
        __syncthreads();

        if (kw + 8 < Kw) {
            pa = *(const uint4*)(Ap + kw + 8);
            if (tid < 128) pb = *(const uint4*)(Bp + kw + 8);
        }

        uint32_t af[2][4], bf[4][2];
        #pragma unroll
        for (int mt = 0; mt < 2; mt++) {
            int rb = (wm * 32 + mt * 16) * AST;
            af[mt][0] = As[rb + g * AST + tig];
            af[mt][1] = As[rb + (g + 8) * AST + tig];
            af[mt][2] = As[rb + g * AST + tig + 4];
            af[mt][3] = As[rb + (g + 8) * AST + tig + 4];
        }
        #pragma unroll
        for (int nt = 0; nt < 4; nt++) {
            int cb = (wn * 32 + nt * 8 + g) * AST;
            bf[nt][0] = Bs[cb + tig];
            bf[nt][1] = Bs[cb + tig + 4];
        }

        #pragma unroll
        for (int mt = 0; mt < 2; mt++)
            #pragma unroll
            for (int nt = 0; nt < 4; nt++)
                MMA_F16(acc[mt][nt], af[mt], bf[nt]);
        __syncthreads();
    }

    if (Cf16) {
        #pragma unroll
        for (int mt = 0; mt < 2; mt++)
            #pragma unroll
            for (int nt = 0; nt < 4; nt++) {
                int row = row0 + wm * 32 + mt * 16 + g;
                int col = col0 + wn * 32 + nt * 8 + 2 * tig;
                ((uint32_t*)Cf16)[((size_t)row * N + col) >> 1] =
                    f2h2(acc[mt][nt][0], acc[mt][nt][1]);
                ((uint32_t*)Cf16)[((size_t)(row + 8) * N + col) >> 1] =
                    f2h2(acc[mt][nt][2], acc[mt][nt][3]);
            }
    } else {
        #pragma unroll
        for (int mt = 0; mt < 2; mt++)
            #pragma unroll
            for (int nt = 0; nt < 4; nt++) {
                int row = row0 + wm * 32 + mt * 16 + g;
                int col = col0 + wn * 32 + nt * 8 + 2 * tig;
                *(float2*)(C + (size_t)row * N + col) =
                    make_float2(acc[mt][nt][0], acc[mt][nt][1]);
                *(float2*)(C + (size_t)(row + 8) * N + col) =
                    make_float2(acc[mt][nt][2], acc[mt][nt][3]);
            }
    }
}

// ---------------------------------------------------------------------------
// Fused RMSNorm + RoPE (table) + scale -> fp16. One launch covers q and k.
// ---------------------------------------------------------------------------
__global__ void rms_rope_f16(const float* __restrict__ qsrc,
                             const float* __restrict__ ksrc,
                             uint16_t* __restrict__ qdst,
                             uint16_t* __restrict__ kdst,
                             const float* __restrict__ ctab,
                             const float* __restrict__ stab)
{
    int w    = (blockIdx.x * blockDim.x + threadIdx.x) >> 5;
    int lane = threadIdx.x & 31;
    const int QROWS = BT_ * NH_;
    if (w >= QROWS + BT_ * NKV_) return;

    const float* src;
    uint16_t* dst;
    int t;
    float scale;
    if (w < QROWS) {
        src = qsrc + (size_t)w * HD_;
        dst = qdst + (size_t)w * HD_;
        t = (w / NH_) % T_;
        scale = 0.125f;
    } else {
        int wk = w - QROWS;
        src = ksrc + (size_t)wk * HD_;
        dst = kdst + (size_t)wk * HD_;
        t = (wk / NKV_) % T_;
        scale = 1.0f;
    }

    float x1 = src[lane], x2 = src[lane + 32];
    float ss = x1 * x1 + x2 * x2;
    #pragma unroll
    for (int o = 16; o; o >>= 1) ss += __shfl_xor_sync(0xffffffffu, ss, o);
    float sc = rsqrtf(ss * (1.0f / HD_) + 1.1920928955078125e-07f);
    x1 *= sc; x2 *= sc;

    float c = ctab[t * 32 + lane], s = stab[t * 32 + lane];
    float o1 = ( x1 * c + x2 * s) * scale;
    float o2 = (-x1 * s + x2 * c) * scale;

    __half h1 = __float2half_rn(o1), h2 = __float2half_rn(o2);
    dst[lane]      = *(uint16_t*)&h1;
    dst[lane + 32] = *(uint16_t*)&h2;
}

// ---------------------------------------------------------------------------
// Tensor-core causal GQA flash attention, single-product fp16, BM=128.
// Writes fp16 y directly (consumed by the fp16 out-projection GEMM).
// ---------------------------------------------------------------------------
__global__ __launch_bounds__(256) void flash_tc(
    const uint16_t* __restrict__ qf, const uint16_t* __restrict__ kf,
    const uint16_t* __restrict__ vf, uint16_t* __restrict__ yf)
{
    __shared__ uint32_t K_s[64*36], V_s[64*36];

    const int b = blockIdx.z, h = blockIdx.y;
    const int m0 = blockIdx.x * 128;
    const int kvh = h >> 1;
    const int tid = threadIdx.x, wid = tid >> 5, lane = tid & 31;
    const int g = lane >> 2, tig = lane & 3;
    const int row0 = m0 + wid * 16;

    const uint32_t* q32 = (const uint32_t*)qf;
    const uint32_t* k32 = (const uint32_t*)kf;
    const uint32_t* v32 = (const uint32_t*)vf;

    uint32_t qfr[4][4];
    {
        size_t q0 = ((size_t)(b * T_ + row0 + g) * NH_ + h) * 32;
        size_t q1 = ((size_t)(b * T_ + row0 + g + 8) * NH_ + h) * 32;
        #pragma unroll
        for (int kk = 0; kk < 4; kk++) {
            qfr[kk][0] = q32[q0 + kk*8 + tig];
            qfr[kk][1] = q32[q1 + kk*8 + tig];
            qfr[kk][2] = q32[q0 + kk*8 + 4 + tig];
            qfr[kk][3] = q32[q1 + kk*8 + 4 + tig];
        }
    }

    float o[8][4];
    #pragma unroll
    for (int nt = 0; nt < 8; nt++)
        #pragma unroll
        for (int c = 0; c < 4; c++) o[nt][c] = 0.f;
    float lsum0 = 0.f, lsum1 = 0.f;

    uint32_t v_base = (uint32_t)__cvta_generic_to_shared(V_s);

    for (int n0 = 0; n0 <= m0 + 64; n0 += 64) {
        #pragma unroll
        for (int it = 0; it < 2; it++) {
            int e = it * 256 + tid;
            int j = e >> 3, dq = (e & 7) * 4;
            size_t src = ((size_t)(b * T_ + n0 + j) * NKV_ + kvh) * 32 + dq;
            int dst = j * 36 + dq;
            *(uint4*)&K_s[dst] = *(const uint4*)&k32[src];
            *(uint4*)&V_s[dst] = *(const uint4*)&v32[src];
        }
        __syncthreads();

        float sfr[8][4];
        #pragma unroll
        for (int nt = 0; nt < 8; nt++) {
            #pragma unroll
            for (int c = 0; c < 4; c++) sfr[nt][c] = 0.f;
            #pragma unroll
            for (int kk = 0; kk < 4; kk++) {
                uint32_t bb[2];
                int bw = (nt*8 + g)*36 + kk*8 + tig;
                bb[0] = K_s[bw]; bb[1] = K_s[bw + 4];
                MMA_F16(sfr[nt], qfr[kk], bb);
            }
        }

        uint32_t pfr[4][4];
        const bool diag = (n0 + 64 > row0);
        #pragma unroll
        for (int nt = 0; nt < 8; nt++) {
            float p0 = __expf(sfr[nt][0]);
            float p1 = __expf(sfr[nt][1]);
            float p2 = __expf(sfr[nt][2]);
            float p3 = __expf(sfr[nt][3]);
            if (diag) {
                int col = n0 + nt*8 + 2*tig;
                int r0 = row0 + g, r1 = row0 + g + 8;
                if (col     > r0) p0 = 0.f;
                if (col + 1 > r0) p1 = 0.f;
                if (col     > r1) p2 = 0.f;
                if (col + 1 > r1) p3 = 0.f;
            }
            lsum0 += p0 + p1;
            lsum1 += p2 + p3;
            int kk = nt >> 1, s = (nt & 1) * 2;
            pfr[kk][s]   = f2h2(p0, p1);
            pfr[kk][s+1] = f2h2(p2, p3);
        }

        #pragma unroll
        for (int nt = 0; nt < 8; nt++) {
            #pragma unroll
            for (int kk = 0; kk < 4; kk++) {
                uint32_t off = ((16*kk + (lane & 15)) * 36 + nt*4) * 4;
                uint32_t bb[2];
                LDMX2T(bb[0], bb[1], v_base + off);
                MMA_F16(o[nt], pfr[kk], bb);
            }
        }
        __syncthreads();
    }

    lsum0 += __shfl_xor_sync(0xffffffffu, lsum0, 1);
    lsum0 += __shfl_xor_sync(0xffffffffu, lsum0, 2);
    lsum1 += __shfl_xor_sync(0xffffffffu, lsum1, 1);
    lsum1 += __shfl_xor_sync(0xffffffffu, lsum1, 2);
    float i0 = 1.f / lsum0, i1 = 1.f / lsum1;

    size_t y0 = ((size_t)(b * T_ + row0 + g) * NH_ + h) * HD_;
    size_t y1 = ((size_t)(b * T_ + row0 + g + 8) * NH_ + h) * HD_;
    #pragma unroll
    for (int nt = 0; nt < 8; nt++) {
        int col = nt*8 + 2*tig;
        ((uint32_t*)yf)[(y0 + col) >> 1] = f2h2(o[nt][0] * i0, o[nt][1] * i0);
        ((uint32_t*)yf)[(y1 + col) >> 1] = f2h2(o[nt][2] * i1, o[nt][3] * i1);
    }
}

// ---------------------------------------------------------------------------
extern "C" void kernel_launch(void* const* d_in, const int* in_sizes, int n_in,
                              void* d_out, int out_size)
{
    const float* x  = (const float*)d_in[0];
    const float* Wq = (const float*)d_in[1];
    const float* Wk = (const float*)d_in[2];
    const float* Wv = (const float*)d_in[3];
    const float* Wp = (const float*)d_in[4];
    float* out = (float*)d_out;

    float *q, *k, *ctab, *stab;
    cudaGetSymbolAddress((void**)&q, g_q);
    cudaGetSymbolAddress((void**)&k, g_k);
    cudaGetSymbolAddress((void**)&ctab, g_cos);
    cudaGetSymbolAddress((void**)&stab, g_sin);
    uint16_t *xf, *wqf, *wkf, *wvf, *wpf, *qf, *kf, *vf, *yf;
    cudaGetSymbolAddress((void**)&xf, g_xf);
    cudaGetSymbolAddress((void**)&wqf, g_wqf);
    cudaGetSymbolAddress((void**)&wkf, g_wkf);
    cudaGetSymbolAddress((void**)&wvf, g_wvf);
    cudaGetSymbolAddress((void**)&wpf, g_wpf);
    cudaGetSymbolAddress((void**)&qf, g_qf);
    cudaGetSymbolAddress((void**)&kf, g_kf);
    cudaGetSymbolAddress((void**)&vf, g_vf);
    cudaGetSymbolAddress((void**)&yf, g_yf);

    // prologue: rope tables + fp16 pre-conversion of x and all weights
    rope_tables<<<(T_*32 + 255)/256, 256>>>(ctab, stab);
    to_f16<<<(BT_*DIM_/4 + 255)/256, 256>>>(x,  xf,  BT_*DIM_/4);
    to_f16<<<(DIM_*DIM_/4 + 255)/256, 256>>>(Wq, wqf, DIM_*DIM_/4);
    to_f16<<<(KVD_*DIM_/4 + 255)/256, 256>>>(Wk, wkf, KVD_*DIM_/4);
    to_f16<<<(KVD_*DIM_/4 + 255)/256, 256>>>(Wv, wvf, KVD_*DIM_/4);
    to_f16<<<(DIM_*DIM_/4 + 255)/256, 256>>>(Wp, wpf, DIM_*DIM_/4);

    // QKV projections: pure fp16 pipeline (V writes fp16 directly)
    gemm_hh<<<dim3(DIM_/GBN, BT_/GBM), 256>>>((uint32_t*)xf, (uint32_t*)wqf,
                                              q, nullptr, BT_, DIM_, DIM_);
    gemm_hh<<<dim3(KVD_/GBN, BT_/GBM), 256>>>((uint32_t*)xf, (uint32_t*)wkf,
                                              k, nullptr, BT_, KVD_, DIM_);
    gemm_hh<<<dim3(KVD_/GBN, BT_/GBM), 256>>>((uint32_t*)xf, (uint32_t*)wvf,
                                              nullptr, vf, BT_, KVD_, DIM_);

    // fused rmsnorm+rope -> fp16 q,k
    rms_rope_f16<<<((BT_*NH_ + BT_*NKV_)*32 + 255)/256, 256>>>(q, k, qf, kf, ctab, stab);

    // fp16 tensor-core causal flash attention (BM=128), fp16 y out
    flash_tc<<<dim3(T_/128, NH_, B_), 256>>>(qf, kf, vf, yf);

    // Output projection: fp16 pipeline, fp32 result
    gemm_hh<<<dim3(DIM_/GBN, BT_/GBM), 256>>>((uint32_t*)yf, (uint32_t*)wpf,
                                              out, nullptr, BT_, DIM_, DIM_);
}